// round 5
// baseline (speedup 1.0000x reference)
#include <cuda_runtime.h>
#include <cuda_bf16.h>
#include <math.h>

#define Bb   4
#define Cc   128
#define DI   256
#define Nn   16
#define Rr   8
#define Kk   4
#define Hh   48
#define Ww   48
#define LL   2304
#define BL   9216
#define SEG  576          // LL/4
#define NSEG 4

// ---------------- scratch (device globals) ----------------
__device__ float g_xn   [(size_t)BL * Cc];
__device__ float g_xz   [(size_t)BL * 2 * DI];
__device__ float g_xhw  [(size_t)Bb * DI * LL];
__device__ float g_xwh  [(size_t)Bb * DI * LL];
__device__ float g_delta[(size_t)Bb * Kk * DI * LL];
__device__ float g_Bm   [(size_t)Bb * Kk * Nn * LL];
__device__ float g_Cm   [(size_t)Bb * Kk * Nn * LL];
__device__ float g_ys   [(size_t)Bb * Kk * DI * LL];
__device__ float g_ycomb[(size_t)BL * DI];
__device__ float g_yact [(size_t)BL * DI];
__device__ float g_hout [(size_t)16 * NSEG * 4096];
__device__ float g_prodA[(size_t)16 * NSEG * 4096];
__device__ float g_hin  [(size_t)16 * NSEG * 4096];

__device__ __forceinline__ float ex2f(float x){
    float r; asm("ex2.approx.f32 %0, %1;" : "=f"(r) : "f"(x)); return r;
}
__device__ __forceinline__ float sigmf(float x){
    return 1.f / (1.f + __expf(-x));
}

// ================= K0: channel LayerNorm -> xn (B*L, C) =================
__global__ void k0_ln(const float* __restrict__ x,
                      const float* __restrict__ lg, const float* __restrict__ lb)
{
    int b = blockIdx.x / Hh;
    int h = blockIdx.x % Hh;
    __shared__ float s[Cc][Ww + 1];
    __shared__ float mu[Ww], rs[Ww];

    const float* xb = x + (size_t)b * Cc * LL + (size_t)h * Ww;
    for (int idx = threadIdx.x; idx < Cc * Ww; idx += 256) {
        int c = idx / Ww, w = idx % Ww;
        s[c][w] = xb[(size_t)c * LL + w];
    }
    __syncthreads();
    if (threadIdx.x < Ww) {
        int w = threadIdx.x;
        float sm = 0.f, sq = 0.f;
        #pragma unroll 8
        for (int c = 0; c < Cc; c++) { float v = s[c][w]; sm += v; sq += v * v; }
        float m = sm * (1.f / Cc);
        float var = sq * (1.f / Cc) - m * m;
        mu[w] = m; rs[w] = rsqrtf(var + 1e-5f);
    }
    __syncthreads();
    float* out = g_xn + ((size_t)(b * LL + h * Ww)) * Cc;
    for (int idx = threadIdx.x; idx < Ww * Cc; idx += 256) {
        int w = idx >> 7, c = idx & 127;
        out[idx] = (s[c][w] - mu[w]) * rs[w] * lg[c] + lb[c];
    }
}

// ================= K1: xz = xn @ in_proj_w^T  (9216 x 512 x 128) =================
__global__ void __launch_bounds__(256) k1_gemm(const float* __restrict__ Wp)
{
    __shared__ float As[16][128];
    __shared__ float Bs[16][128];
    int m0 = blockIdx.x * 128, n0 = blockIdx.y * 128;
    int tid = threadIdx.x;
    int tm = tid & 15, tn = tid >> 4;
    int row = tid >> 1, kq = (tid & 1) * 8;
    float acc[8][8];
    #pragma unroll
    for (int i = 0; i < 8; i++)
        #pragma unroll
        for (int j = 0; j < 8; j++) acc[i][j] = 0.f;

    for (int k0 = 0; k0 < Cc; k0 += 16) {
        float4 a0 = *(const float4*)(g_xn + (size_t)(m0 + row) * Cc + k0 + kq);
        float4 a1 = *(const float4*)(g_xn + (size_t)(m0 + row) * Cc + k0 + kq + 4);
        float4 b0 = *(const float4*)(Wp   + (size_t)(n0 + row) * Cc + k0 + kq);
        float4 b1 = *(const float4*)(Wp   + (size_t)(n0 + row) * Cc + k0 + kq + 4);
        __syncthreads();
        As[kq+0][row]=a0.x; As[kq+1][row]=a0.y; As[kq+2][row]=a0.z; As[kq+3][row]=a0.w;
        As[kq+4][row]=a1.x; As[kq+5][row]=a1.y; As[kq+6][row]=a1.z; As[kq+7][row]=a1.w;
        Bs[kq+0][row]=b0.x; Bs[kq+1][row]=b0.y; Bs[kq+2][row]=b0.z; Bs[kq+3][row]=b0.w;
        Bs[kq+4][row]=b1.x; Bs[kq+5][row]=b1.y; Bs[kq+6][row]=b1.z; Bs[kq+7][row]=b1.w;
        __syncthreads();
        #pragma unroll
        for (int kk = 0; kk < 16; kk++) {
            float4 av0 = *(const float4*)&As[kk][tm << 3];
            float4 av1 = *(const float4*)&As[kk][(tm << 3) + 4];
            float4 bv0 = *(const float4*)&Bs[kk][tn << 3];
            float4 bv1 = *(const float4*)&Bs[kk][(tn << 3) + 4];
            float am[8] = {av0.x,av0.y,av0.z,av0.w,av1.x,av1.y,av1.z,av1.w};
            float bn[8] = {bv0.x,bv0.y,bv0.z,bv0.w,bv1.x,bv1.y,bv1.z,bv1.w};
            #pragma unroll
            for (int i = 0; i < 8; i++)
                #pragma unroll
                for (int j = 0; j < 8; j++)
                    acc[i][j] = fmaf(am[i], bn[j], acc[i][j]);
        }
    }
    #pragma unroll
    for (int i = 0; i < 8; i++) {
        float* o = g_xz + (size_t)(m0 + (tm << 3) + i) * 512 + n0 + (tn << 3);
        *(float4*)o       = make_float4(acc[i][0], acc[i][1], acc[i][2], acc[i][3]);
        *(float4*)(o + 4) = make_float4(acc[i][4], acc[i][5], acc[i][6], acc[i][7]);
    }
}

// ================= K2: depthwise conv3x3 + bias + SiLU -> x_hw, x_wh =================
__global__ void k2_conv(const float* __restrict__ cw, const float* __restrict__ cb)
{
    int bi  = blockIdx.x;
    int dci = bi & 15;
    int hci = (bi >> 4) % 6;
    int b   = bi / 96;
    int d0  = dci * 16;
    int hc  = hci * 8;
    int tid = threadIdx.x;

    __shared__ float sbuf[10][Ww][17];
    __shared__ float wgt[16][9];
    __shared__ float bia[16];

    if (tid < 144) wgt[tid / 9][tid % 9] = cw[(size_t)(d0 + tid / 9) * 9 + tid % 9];
    if (tid >= 144 && tid < 160) bia[tid - 144] = cb[d0 + tid - 144];

    for (int idx = tid; idx < 10 * Ww * 16; idx += 256) {
        int d = idx & 15;
        int rest = idx >> 4;
        int w = rest % Ww;
        int hh = rest / Ww;
        int gh = hc - 1 + hh;
        float v = 0.f;
        if (gh >= 0 && gh < Hh)
            v = g_xz[((size_t)(b * LL + gh * Ww + w)) * 512 + d0 + d];
        sbuf[hh][w][d] = v;
    }
    __syncthreads();

    float outv[24];
    #pragma unroll
    for (int it = 0; it < 24; it++) {
        int idx = tid + it * 256;
        int d = idx / 384;
        int r = idx % 384;
        int h = r / Ww;
        int w = r % Ww;
        float sum = bia[d];
        #pragma unroll
        for (int i = 0; i < 3; i++) {
            #pragma unroll
            for (int j = 0; j < 3; j++) {
                int ww = w + j - 1;
                float xv = (ww >= 0 && ww < Ww) ? sbuf[h + i][ww][d] : 0.f;
                sum = fmaf(wgt[d][i * 3 + j], xv, sum);
            }
        }
        outv[it] = sum * sigmf(sum);
    }
    __syncthreads();
    #pragma unroll
    for (int it = 0; it < 24; it++) {
        int idx = tid + it * 256;
        int d = idx / 384; int r = idx % 384; int h = r / Ww; int w = r % Ww;
        g_xhw[((size_t)(b * DI + d0 + d)) * LL + (hc + h) * Ww + w] = outv[it];
        sbuf[h][w][d] = outv[it];
    }
    __syncthreads();
    for (int it = 0; it < 24; it++) {
        int idx = tid + it * 256;
        int d = idx / 384; int r = idx % 384; int w = r >> 3; int h = r & 7;
        g_xwh[((size_t)(b * DI + d0 + d)) * LL + w * Hh + hc + h] = sbuf[h][w][d];
    }
}

// ================= K3: x_proj + dt projection + softplus (64-l tiles, 4 q-groups) =================
__global__ void __launch_bounds__(256) k3_xproj(const float* __restrict__ xpw,
                         const float* __restrict__ dtwg,
                         const float* __restrict__ dtbg)
{
    int lt = blockIdx.x % 36;
    int bk = blockIdx.x / 36;
    int k  = bk & 3;
    int b  = bk >> 2;
    int l0 = lt * 64;
    int tid = threadIdx.x;
    int ll = tid & 63, q = tid >> 6;     // q in 0..3

    __shared__ float xd[40][64];
    __shared__ float wp2[32][4][10];
    __shared__ float dtw[DI * Rr];

    const float* usrc = (((k & 1) == 0) ? g_xhw : g_xwh) + (size_t)b * DI * LL;
    bool rev = (k >= 2);
    int gl = rev ? (LL - 1 - (l0 + ll)) : (l0 + ll);

    for (int idx = tid; idx < DI * Rr; idx += 256)
        dtw[idx] = dtwg[(size_t)k * DI * Rr + idx];

    float acc[10];
    #pragma unroll
    for (int j = 0; j < 10; j++) acc[j] = 0.f;

    for (int dc = 0; dc < DI; dc += 32) {
        __syncthreads();
        for (int idx = tid; idx < 1280; idx += 256) {
            int c = idx >> 5, dd = idx & 31;
            wp2[dd][c & 3][c >> 2] = xpw[(size_t)(k * 40 + c) * DI + dc + dd];
        }
        __syncthreads();
        #pragma unroll
        for (int dd0 = 0; dd0 < 32; dd0 += 8) {
            float uv[8];
            #pragma unroll
            for (int i = 0; i < 8; i++)
                uv[i] = usrc[(size_t)(dc + dd0 + i) * LL + gl];
            #pragma unroll
            for (int i = 0; i < 8; i++) {
                const float* w = &wp2[dd0 + i][q][0];
                float u = uv[i];
                #pragma unroll
                for (int j = 0; j < 10; j++) acc[j] = fmaf(w[j], u, acc[j]);
            }
        }
    }
    __syncthreads();
    #pragma unroll
    for (int j = 0; j < 10; j++) xd[q + 4 * j][ll] = acc[j];
    __syncthreads();

    for (int idx = tid; idx < Nn * 64; idx += 256) {
        int nn = idx >> 6, li = idx & 63;
        g_Bm[((size_t)bk * Nn + nn) * LL + l0 + li] = xd[Rr + nn][li];
        g_Cm[((size_t)bk * Nn + nn) * LL + l0 + li] = xd[Rr + Nn + nn][li];
    }
    float dtr[8];
    #pragma unroll
    for (int r = 0; r < 8; r++) dtr[r] = xd[r][ll];

    const float* dtb = dtbg + k * DI;
    #pragma unroll 2
    for (int dd = 0; dd < 64; dd++) {
        int d = (q << 6) + dd;
        float4 w0 = *(const float4*)&dtw[d * 8];
        float4 w1 = *(const float4*)&dtw[d * 8 + 4];
        float a = dtb[d];
        a = fmaf(w0.x, dtr[0], a); a = fmaf(w0.y, dtr[1], a);
        a = fmaf(w0.z, dtr[2], a); a = fmaf(w0.w, dtr[3], a);
        a = fmaf(w1.x, dtr[4], a); a = fmaf(w1.y, dtr[5], a);
        a = fmaf(w1.z, dtr[6], a); a = fmaf(w1.w, dtr[7], a);
        float sp = fmaxf(a, 0.f) + __logf(1.f + __expf(-fabsf(a)));
        g_delta[((size_t)bk * DI + d) * LL + l0 + ll] = sp;
    }
}

// ================= K4a: segmented scan pass (4 segments, h0=0) =================
__global__ void __launch_bounds__(128) k4a_scan(const float* __restrict__ A_logs,
                                                const float* __restrict__ Ds)
{
    int bx = blockIdx.x;
    int dg  = bx & 31;
    int bk  = (bx >> 5) & 15;
    int seg = bx >> 9;
    int k  = bk & 3;
    int b  = bk >> 2;
    int lane = threadIdx.x & 31;
    int warp = threadIdx.x >> 5;
    int half = lane >> 4;
    int n    = lane & 15;
    int d    = dg * 8 + warp * 2 + half;

    float aa   = -expf(A_logs[((size_t)(k * DI + d)) * Nn + n]) * 1.44269504088896f;
    float Dv16 = Ds[k * DI + d] * 0.0625f;

    const float* dp = g_delta + ((size_t)bk * DI + d) * LL;
    const float* up = ((((k & 1) == 0) ? g_xhw : g_xwh)) + ((size_t)(b * DI + d)) * LL;
    const float* Bp = g_Bm + ((size_t)bk * Nn + n) * LL;
    const float* Cp = g_Cm + ((size_t)bk * Nn + n) * LL;
    const bool rev = (k >= 2);

    int ln4 = lane & 15;
    int vsel = (((ln4 >> 3) & 1) << 2) | (((ln4 >> 2) & 1) << 1) | ((ln4 >> 1) & 1);
    bool wlane = ((lane & 1) == 0);

    __shared__ float yb[4][2][64];
    float h = 0.f, sumd = 0.f;
    int t00 = seg * SEG;
    int tend = t00 + SEG;

#define LOADC(T, Dq0,Dq1,Uq0,Uq1,Bq0,Bq1,Cq0,Cq1)                              \
    {   int _t = (T);                                                          \
        Dq0 = *(const float4*)(dp + _t); Dq1 = *(const float4*)(dp + _t + 4);  \
        Bq0 = *(const float4*)(Bp + _t); Bq1 = *(const float4*)(Bp + _t + 4);  \
        Cq0 = *(const float4*)(Cp + _t); Cq1 = *(const float4*)(Cp + _t + 4);  \
        if (!rev) { Uq0 = *(const float4*)(up + _t); Uq1 = *(const float4*)(up + _t + 4); } \
        else {                                                                 \
            float4 p0 = *(const float4*)(up + (LL - 8 - _t));                  \
            float4 p1 = *(const float4*)(up + (LL - 4 - _t));                  \
            Uq0.x = p1.w; Uq0.y = p1.z; Uq0.z = p1.y; Uq0.w = p1.x;            \
            Uq1.x = p0.w; Uq1.y = p0.z; Uq1.z = p0.y; Uq1.w = p0.x; } }

    float4 D0,D1,U0,U1,Bq0,Bq1,Cq0,Cq1;
    LOADC(t00, D0,D1,U0,U1,Bq0,Bq1,Cq0,Cq1)

    #pragma unroll 2
    for (int t0 = t00; t0 < tend; t0 += 8) {
        float4 nD0,nD1,nU0,nU1,nB0,nB1,nC0,nC1;
        nD0=D0; nD1=D1; nU0=U0; nU1=U1; nB0=Bq0; nB1=Bq1; nC0=Cq0; nC1=Cq1;
        if (t0 + 8 < tend) LOADC(t0 + 8, nD0,nD1,nU0,nU1,nB0,nB1,nC0,nC1)

        float dl[8] = {D0.x,D0.y,D0.z,D0.w,D1.x,D1.y,D1.z,D1.w};
        float uu[8] = {U0.x,U0.y,U0.z,U0.w,U1.x,U1.y,U1.z,U1.w};
        float bb[8] = {Bq0.x,Bq0.y,Bq0.z,Bq0.w,Bq1.x,Bq1.y,Bq1.z,Bq1.w};
        float cc[8] = {Cq0.x,Cq0.y,Cq0.z,Cq0.w,Cq1.x,Cq1.y,Cq1.z,Cq1.w};
        float ee[8], p[8];
        #pragma unroll
        for (int i = 0; i < 8; i++) ee[i] = ex2f(dl[i] * aa);
        #pragma unroll
        for (int i = 0; i < 8; i++) {
            h = fmaf(h, ee[i], (dl[i] * uu[i]) * bb[i]);
            p[i] = fmaf(Dv16, uu[i], h * cc[i]);
            sumd += dl[i];
        }
        #pragma unroll
        for (int i = 0; i < 8; i++) p[i] += __shfl_xor_sync(0xffffffffu, p[i], 8);
        float q0 = (lane & 8) ? p[4] : p[0];
        float q1 = (lane & 8) ? p[5] : p[1];
        float q2 = (lane & 8) ? p[6] : p[2];
        float q3 = (lane & 8) ? p[7] : p[3];
        q0 += __shfl_xor_sync(0xffffffffu, q0, 4);
        q1 += __shfl_xor_sync(0xffffffffu, q1, 4);
        q2 += __shfl_xor_sync(0xffffffffu, q2, 4);
        q3 += __shfl_xor_sync(0xffffffffu, q3, 4);
        float r0 = (lane & 4) ? q2 : q0;
        float r1 = (lane & 4) ? q3 : q1;
        r0 += __shfl_xor_sync(0xffffffffu, r0, 2);
        r1 += __shfl_xor_sync(0xffffffffu, r1, 2);
        float s = (lane & 2) ? r1 : r0;
        s += __shfl_xor_sync(0xffffffffu, s, 1);
        if (wlane) yb[warp][half][(t0 & 63) + vsel] = s;

        if ((t0 & 63) == 56) {
            __syncwarp();
            int idx = lane * 4, hs = idx >> 6, off = idx & 63;
            float4 v = *(float4*)&yb[warp][hs][off];
            *(float4*)(g_ys + ((size_t)bk * DI + dg * 8 + warp * 2 + hs) * LL + (t0 - 56) + off) = v;
            __syncwarp();
        }
        D0=nD0; D1=nD1; U0=nU0; U1=nU1; Bq0=nB0; Bq1=nB1; Cq0=nC0; Cq1=nC1;
    }
#undef LOADC
    size_t hoff = ((size_t)(bk * NSEG + seg)) * 4096 + (size_t)d * 16 + n;
    g_hout [hoff] = h;
    g_prodA[hoff] = ex2f(aa * sumd);
}

// ================= K4b: segment carry fix-up =================
__global__ void k4b_fix()
{
    int idx = blockIdx.x * 256 + threadIdx.x;    // 0..65535
    int bk = idx >> 12;
    int dn = idx & 4095;
    float hin = 0.f;
    #pragma unroll
    for (int seg = 0; seg < NSEG; seg++) {
        size_t off = ((size_t)(bk * NSEG + seg)) * 4096 + dn;
        g_hin[off] = hin;
        float ho = g_hout[off];
        float pa = g_prodA[off];
        hin = fmaf(pa, hin, ho);
    }
}

// ================= K4c: carry-in correction for segments 1..3 =================
__global__ void __launch_bounds__(128) k4c_corr(const float* __restrict__ A_logs)
{
    int bx = blockIdx.x;
    int dg  = bx & 31;
    int bk  = (bx >> 5) & 15;
    int seg = 1 + (bx >> 9);
    int k  = bk & 3;
    int lane = threadIdx.x & 31;
    int warp = threadIdx.x >> 5;
    int half = lane >> 4;
    int n    = lane & 15;
    int d    = dg * 8 + warp * 2 + half;

    float aa = -expf(A_logs[((size_t)(k * DI + d)) * Nn + n]) * 1.44269504088896f;
    float hin = g_hin[((size_t)(bk * NSEG + seg)) * 4096 + (size_t)d * 16 + n];

    const float* dp = g_delta + ((size_t)bk * DI + d) * LL;
    const float* Cp = g_Cm + ((size_t)bk * Nn + n) * LL;

    int ln4 = lane & 15;
    int vsel = (((ln4 >> 3) & 1) << 2) | (((ln4 >> 2) & 1) << 1) | ((ln4 >> 1) & 1);
    bool wlane = ((lane & 1) == 0);

    __shared__ float yb[4][2][64];
    float cum = 0.f;
    int t00 = seg * SEG;
    int tend = t00 + SEG;

    float4 D0 = *(const float4*)(dp + t00);
    float4 D1 = *(const float4*)(dp + t00 + 4);
    float4 C0 = *(const float4*)(Cp + t00);
    float4 C1 = *(const float4*)(Cp + t00 + 4);

    #pragma unroll 2
    for (int t0 = t00; t0 < tend; t0 += 8) {
        float4 nD0=D0, nD1=D1, nC0=C0, nC1=C1;
        if (t0 + 8 < tend) {
            nD0 = *(const float4*)(dp + t0 + 8);  nD1 = *(const float4*)(dp + t0 + 12);
            nC0 = *(const float4*)(Cp + t0 + 8);  nC1 = *(const float4*)(Cp + t0 + 12);
        }
        float dl[8] = {D0.x,D0.y,D0.z,D0.w,D1.x,D1.y,D1.z,D1.w};
        float cc[8] = {C0.x,C0.y,C0.z,C0.w,C1.x,C1.y,C1.z,C1.w};
        float cs[8], p[8];
        cs[0] = cum + dl[0];
        #pragma unroll
        for (int i = 1; i < 8; i++) cs[i] = cs[i-1] + dl[i];
        cum = cs[7];
        #pragma unroll
        for (int i = 0; i < 8; i++)
            p[i] = (hin * ex2f(aa * cs[i])) * cc[i];

        #pragma unroll
        for (int i = 0; i < 8; i++) p[i] += __shfl_xor_sync(0xffffffffu, p[i], 8);
        float q0 = (lane & 8) ? p[4] : p[0];
        float q1 = (lane & 8) ? p[5] : p[1];
        float q2 = (lane & 8) ? p[6] : p[2];
        float q3 = (lane & 8) ? p[7] : p[3];
        q0 += __shfl_xor_sync(0xffffffffu, q0, 4);
        q1 += __shfl_xor_sync(0xffffffffu, q1, 4);
        q2 += __shfl_xor_sync(0xffffffffu, q2, 4);
        q3 += __shfl_xor_sync(0xffffffffu, q3, 4);
        float r0 = (lane & 4) ? q2 : q0;
        float r1 = (lane & 4) ? q3 : q1;
        r0 += __shfl_xor_sync(0xffffffffu, r0, 2);
        r1 += __shfl_xor_sync(0xffffffffu, r1, 2);
        float s = (lane & 2) ? r1 : r0;
        s += __shfl_xor_sync(0xffffffffu, s, 1);
        if (wlane) yb[warp][half][(t0 & 63) + vsel] = s;

        if ((t0 & 63) == 56) {
            __syncwarp();
            int idx = lane * 4, hs = idx >> 6, off = idx & 63;
            float* gp = g_ys + ((size_t)bk * DI + dg * 8 + warp * 2 + hs) * LL + (t0 - 56) + off;
            float4 cur = *(float4*)gp;
            float4 v = *(float4*)&yb[warp][hs][off];
            *(float4*)gp = make_float4(cur.x + v.x, cur.y + v.y, cur.z + v.z, cur.w + v.w);
            __syncwarp();
        }
        D0=nD0; D1=nD1; C0=nC0; C1=nC1;
    }
}

// ================= K5: combine the four direction outputs =================
__global__ void k5_combine()
{
    int hc = blockIdx.x % 6;
    int dc = (blockIdx.x / 6) & 15;
    int b  = blockIdx.x / 96;
    int d0 = dc * 16, h0 = hc * 8;
    __shared__ float s[16][392];
    int tid = threadIdx.x;
    const float* y0 = g_ys + ((size_t)(b * 4 + 0) * DI + d0) * LL;
    const float* y1 = g_ys + ((size_t)(b * 4 + 1) * DI + d0) * LL;
    const float* y2 = g_ys + ((size_t)(b * 4 + 2) * DI + d0) * LL;
    const float* y3 = g_ys + ((size_t)(b * 4 + 3) * DI + d0) * LL;
    int base = h0 * Ww;

    for (int idx = tid; idx < 16 * 384; idx += 256) {
        int d = idx / 384, p = idx % 384;
        int l = base + p;
        s[d][p] = y0[(size_t)d * LL + l] + y2[(size_t)d * LL + (LL - 1 - l)];
    }
    __syncthreads();
    for (int idx = tid; idx < 16 * 384; idx += 256) {
        int d = idx / 384, p = idx % 384;
        int w = p >> 3, hh = p & 7;
        int t1 = w * Hh + h0 + hh;
        float v = y1[(size_t)d * LL + t1] + y3[(size_t)d * LL + (LL - 1 - t1)];
        s[d][hh * Ww + w] += v;
    }
    __syncthreads();
    for (int idx = tid; idx < 384 * 16; idx += 256) {
        int p = idx >> 4, d = idx & 15;
        g_ycomb[((size_t)(b * LL + base + p)) * DI + d0 + d] = s[d][p];
    }
}

// ================= K6: LayerNorm(DI) + SiLU(z) gate =================
__global__ void k6_lngate(const float* __restrict__ og, const float* __restrict__ ob)
{
    int m = blockIdx.x;
    int tid = threadIdx.x;
    float v = g_ycomb[(size_t)m * DI + tid];
    float sm = v, sq = v * v;
    #pragma unroll
    for (int o = 16; o; o >>= 1) {
        sm += __shfl_xor_sync(0xffffffffu, sm, o);
        sq += __shfl_xor_sync(0xffffffffu, sq, o);
    }
    __shared__ float rs1[8], rs2[8];
    int w = tid >> 5, ln = tid & 31;
    if (ln == 0) { rs1[w] = sm; rs2[w] = sq; }
    __syncthreads();
    float ts = 0.f, tq = 0.f;
    #pragma unroll
    for (int i = 0; i < 8; i++) { ts += rs1[i]; tq += rs2[i]; }
    float mean = ts * (1.f / DI);
    float var  = tq * (1.f / DI) - mean * mean;
    float rstd = rsqrtf(var + 1e-5f);
    float zv = g_xz[(size_t)m * 512 + DI + tid];
    float gate = zv * sigmf(zv);
    g_yact[(size_t)m * DI + tid] = ((v - mean) * rstd * og[tid] + ob[tid]) * gate;
}

// ================= K7: out = x + (yact @ out_proj_w^T), (B,C,L) layout =================
__global__ void __launch_bounds__(256) k7_out(const float* __restrict__ Wout,
                                              const float* __restrict__ x,
                                              float* __restrict__ out)
{
    int b  = blockIdx.z;
    int c0 = blockIdx.x * 64;
    int l0 = blockIdx.y * 128;
    __shared__ float As[16][64];
    __shared__ float Bs[16][128];
    int tid = threadIdx.x;
    int tm = tid & 15, tn = tid >> 4;
    int arow = tid >> 2, akq = (tid & 3) * 4;
    int brow = tid >> 1, bkq = (tid & 1) * 8;
    float acc[4][8];
    #pragma unroll
    for (int i = 0; i < 4; i++)
        #pragma unroll
        for (int j = 0; j < 8; j++) acc[i][j] = 0.f;

    const float* Y = g_yact + (size_t)b * LL * DI;
    for (int k0 = 0; k0 < DI; k0 += 16) {
        float4 a0 = *(const float4*)(Wout + (size_t)(c0 + arow) * DI + k0 + akq);
        float4 b0 = *(const float4*)(Y + (size_t)(l0 + brow) * DI + k0 + bkq);
        float4 b1 = *(const float4*)(Y + (size_t)(l0 + brow) * DI + k0 + bkq + 4);
        __syncthreads();
        As[akq+0][arow]=a0.x; As[akq+1][arow]=a0.y; As[akq+2][arow]=a0.z; As[akq+3][arow]=a0.w;
        Bs[bkq+0][brow]=b0.x; Bs[bkq+1][brow]=b0.y; Bs[bkq+2][brow]=b0.z; Bs[bkq+3][brow]=b0.w;
        Bs[bkq+4][brow]=b1.x; Bs[bkq+5][brow]=b1.y; Bs[bkq+6][brow]=b1.z; Bs[bkq+7][brow]=b1.w;
        __syncthreads();
        #pragma unroll
        for (int kk = 0; kk < 16; kk++) {
            float4 av  = *(const float4*)&As[kk][tm << 2];
            float4 bv0 = *(const float4*)&Bs[kk][tn << 3];
            float4 bv1 = *(const float4*)&Bs[kk][(tn << 3) + 4];
            float am[4] = {av.x, av.y, av.z, av.w};
            float bn[8] = {bv0.x,bv0.y,bv0.z,bv0.w,bv1.x,bv1.y,bv1.z,bv1.w};
            #pragma unroll
            for (int i = 0; i < 4; i++)
                #pragma unroll
                for (int j = 0; j < 8; j++)
                    acc[i][j] = fmaf(am[i], bn[j], acc[i][j]);
        }
    }
    #pragma unroll
    for (int i = 0; i < 4; i++) {
        int c = c0 + (tm << 2) + i;
        size_t off = ((size_t)b * Cc + c) * LL + l0 + (tn << 3);
        float4 x0 = *(const float4*)(x + off);
        float4 x1 = *(const float4*)(x + off + 4);
        *(float4*)(out + off)     = make_float4(acc[i][0]+x0.x, acc[i][1]+x0.y, acc[i][2]+x0.z, acc[i][3]+x0.w);
        *(float4*)(out + off + 4) = make_float4(acc[i][4]+x1.x, acc[i][5]+x1.y, acc[i][6]+x1.z, acc[i][7]+x1.w);
    }
}

extern "C" void kernel_launch(void* const* d_in, const int* in_sizes, int n_in,
                              void* d_out, int out_size)
{
    const float* x          = (const float*)d_in[0];
    const float* ln1_g      = (const float*)d_in[1];
    const float* ln1_b      = (const float*)d_in[2];
    const float* in_proj_w  = (const float*)d_in[3];
    const float* conv_w     = (const float*)d_in[4];
    const float* conv_b     = (const float*)d_in[5];
    const float* x_proj_w   = (const float*)d_in[6];
    const float* dt_w       = (const float*)d_in[7];
    const float* dt_b       = (const float*)d_in[8];
    const float* A_logs     = (const float*)d_in[9];
    const float* Ds         = (const float*)d_in[10];
    const float* outn_g     = (const float*)d_in[11];
    const float* outn_b     = (const float*)d_in[12];
    const float* out_proj_w = (const float*)d_in[13];
    float* out = (float*)d_out;

    k0_ln<<<Bb * Hh, 256>>>(x, ln1_g, ln1_b);
    { dim3 g(BL / 128, 512 / 128); k1_gemm<<<g, 256>>>(in_proj_w); }
    k2_conv<<<Bb * 6 * 16, 256>>>(conv_w, conv_b);
    k3_xproj<<<Bb * Kk * 36, 256>>>(x_proj_w, dt_w, dt_b);
    k4a_scan<<<32 * 16 * NSEG, 128>>>(A_logs, Ds);
    k4b_fix<<<256, 256>>>();
    k4c_corr<<<32 * 16 * 3, 128>>>(A_logs);
    k5_combine<<<Bb * 16 * 6, 256>>>();
    k6_lngate<<<BL, 256>>>(outn_g, outn_b);
    { dim3 g(2, 18, Bb); k7_out<<<g, 256>>>(out_proj_w, x, out); }
}

// round 6
// speedup vs baseline: 1.9203x; 1.9203x over previous
#include <cuda_runtime.h>
#include <cuda_bf16.h>
#include <math.h>

#define Bb   4
#define Cc   128
#define DI   256
#define Nn   16
#define Rr   8
#define Kk   4
#define Hh   48
#define Ww   48
#define LL   2304
#define BL   9216

// ---------------- scratch (device globals) ----------------
__device__ float g_xn   [(size_t)BL * Cc];
__device__ float g_xz   [(size_t)BL * 2 * DI];
__device__ float g_xhw  [(size_t)Bb * DI * LL];
__device__ float g_xwh  [(size_t)Bb * DI * LL];
__device__ float g_delta[(size_t)Bb * Kk * DI * LL];
__device__ float g_Bm   [(size_t)Bb * Kk * Nn * LL];
__device__ float g_Cm   [(size_t)Bb * Kk * Nn * LL];
__device__ float g_ys   [(size_t)Bb * Kk * DI * LL];
__device__ float g_ycomb[(size_t)BL * DI];
__device__ float g_yact [(size_t)BL * DI];

__device__ __forceinline__ float ex2f(float x){
    float r; asm("ex2.approx.f32 %0, %1;" : "=f"(r) : "f"(x)); return r;
}
__device__ __forceinline__ float sigmf(float x){
    return 1.f / (1.f + __expf(-x));
}

// ================= K0: channel LayerNorm -> xn (B*L, C) =================
__global__ void k0_ln(const float* __restrict__ x,
                      const float* __restrict__ lg, const float* __restrict__ lb)
{
    int b = blockIdx.x / Hh;
    int h = blockIdx.x % Hh;
    __shared__ float s[Cc][Ww + 1];
    __shared__ float mu[Ww], rs[Ww];

    const float* xb = x + (size_t)b * Cc * LL + (size_t)h * Ww;
    for (int idx = threadIdx.x; idx < Cc * Ww; idx += 256) {
        int c = idx / Ww, w = idx % Ww;
        s[c][w] = xb[(size_t)c * LL + w];
    }
    __syncthreads();
    if (threadIdx.x < Ww) {
        int w = threadIdx.x;
        float sm = 0.f, sq = 0.f;
        #pragma unroll 8
        for (int c = 0; c < Cc; c++) { float v = s[c][w]; sm += v; sq += v * v; }
        float m = sm * (1.f / Cc);
        float var = sq * (1.f / Cc) - m * m;
        mu[w] = m; rs[w] = rsqrtf(var + 1e-5f);
    }
    __syncthreads();
    float* out = g_xn + ((size_t)(b * LL + h * Ww)) * Cc;
    for (int idx = threadIdx.x; idx < Ww * Cc; idx += 256) {
        int w = idx >> 7, c = idx & 127;
        out[idx] = (s[c][w] - mu[w]) * rs[w] * lg[c] + lb[c];
    }
}

// ================= K1: xz = xn @ in_proj_w^T  (9216 x 512 x 128) =================
__global__ void __launch_bounds__(256) k1_gemm(const float* __restrict__ Wp)
{
    __shared__ float As[16][128];
    __shared__ float Bs[16][128];
    int m0 = blockIdx.x * 128, n0 = blockIdx.y * 128;
    int tid = threadIdx.x;
    int tm = tid & 15, tn = tid >> 4;
    int row = tid >> 1, kq = (tid & 1) * 8;
    float acc[8][8];
    #pragma unroll
    for (int i = 0; i < 8; i++)
        #pragma unroll
        for (int j = 0; j < 8; j++) acc[i][j] = 0.f;

    for (int k0 = 0; k0 < Cc; k0 += 16) {
        float4 a0 = *(const float4*)(g_xn + (size_t)(m0 + row) * Cc + k0 + kq);
        float4 a1 = *(const float4*)(g_xn + (size_t)(m0 + row) * Cc + k0 + kq + 4);
        float4 b0 = *(const float4*)(Wp   + (size_t)(n0 + row) * Cc + k0 + kq);
        float4 b1 = *(const float4*)(Wp   + (size_t)(n0 + row) * Cc + k0 + kq + 4);
        __syncthreads();
        As[kq+0][row]=a0.x; As[kq+1][row]=a0.y; As[kq+2][row]=a0.z; As[kq+3][row]=a0.w;
        As[kq+4][row]=a1.x; As[kq+5][row]=a1.y; As[kq+6][row]=a1.z; As[kq+7][row]=a1.w;
        Bs[kq+0][row]=b0.x; Bs[kq+1][row]=b0.y; Bs[kq+2][row]=b0.z; Bs[kq+3][row]=b0.w;
        Bs[kq+4][row]=b1.x; Bs[kq+5][row]=b1.y; Bs[kq+6][row]=b1.z; Bs[kq+7][row]=b1.w;
        __syncthreads();
        #pragma unroll
        for (int kk = 0; kk < 16; kk++) {
            float4 av0 = *(const float4*)&As[kk][tm << 3];
            float4 av1 = *(const float4*)&As[kk][(tm << 3) + 4];
            float4 bv0 = *(const float4*)&Bs[kk][tn << 3];
            float4 bv1 = *(const float4*)&Bs[kk][(tn << 3) + 4];
            float am[8] = {av0.x,av0.y,av0.z,av0.w,av1.x,av1.y,av1.z,av1.w};
            float bn[8] = {bv0.x,bv0.y,bv0.z,bv0.w,bv1.x,bv1.y,bv1.z,bv1.w};
            #pragma unroll
            for (int i = 0; i < 8; i++)
                #pragma unroll
                for (int j = 0; j < 8; j++)
                    acc[i][j] = fmaf(am[i], bn[j], acc[i][j]);
        }
    }
    #pragma unroll
    for (int i = 0; i < 8; i++) {
        float* o = g_xz + (size_t)(m0 + (tm << 3) + i) * 512 + n0 + (tn << 3);
        *(float4*)o       = make_float4(acc[i][0], acc[i][1], acc[i][2], acc[i][3]);
        *(float4*)(o + 4) = make_float4(acc[i][4], acc[i][5], acc[i][6], acc[i][7]);
    }
}

// ================= K2: depthwise conv3x3 + bias + SiLU -> x_hw, x_wh =================
__global__ void k2_conv(const float* __restrict__ cw, const float* __restrict__ cb)
{
    int bi  = blockIdx.x;
    int dci = bi & 15;
    int hci = (bi >> 4) % 6;
    int b   = bi / 96;
    int d0  = dci * 16;
    int hc  = hci * 8;
    int tid = threadIdx.x;

    __shared__ float sbuf[10][Ww][17];
    __shared__ float wgt[16][9];
    __shared__ float bia[16];

    if (tid < 144) wgt[tid / 9][tid % 9] = cw[(size_t)(d0 + tid / 9) * 9 + tid % 9];
    if (tid >= 144 && tid < 160) bia[tid - 144] = cb[d0 + tid - 144];

    for (int idx = tid; idx < 10 * Ww * 16; idx += 256) {
        int d = idx & 15;
        int rest = idx >> 4;
        int w = rest % Ww;
        int hh = rest / Ww;
        int gh = hc - 1 + hh;
        float v = 0.f;
        if (gh >= 0 && gh < Hh)
            v = g_xz[((size_t)(b * LL + gh * Ww + w)) * 512 + d0 + d];
        sbuf[hh][w][d] = v;
    }
    __syncthreads();

    float outv[24];
    #pragma unroll
    for (int it = 0; it < 24; it++) {
        int idx = tid + it * 256;
        int d = idx / 384;
        int r = idx % 384;
        int h = r / Ww;
        int w = r % Ww;
        float sum = bia[d];
        #pragma unroll
        for (int i = 0; i < 3; i++) {
            #pragma unroll
            for (int j = 0; j < 3; j++) {
                int ww = w + j - 1;
                float xv = (ww >= 0 && ww < Ww) ? sbuf[h + i][ww][d] : 0.f;
                sum = fmaf(wgt[d][i * 3 + j], xv, sum);
            }
        }
        outv[it] = sum * sigmf(sum);
    }
    __syncthreads();
    #pragma unroll
    for (int it = 0; it < 24; it++) {
        int idx = tid + it * 256;
        int d = idx / 384; int r = idx % 384; int h = r / Ww; int w = r % Ww;
        g_xhw[((size_t)(b * DI + d0 + d)) * LL + (hc + h) * Ww + w] = outv[it];
        sbuf[h][w][d] = outv[it];
    }
    __syncthreads();
    for (int it = 0; it < 24; it++) {
        int idx = tid + it * 256;
        int d = idx / 384; int r = idx % 384; int w = r >> 3; int h = r & 7;
        g_xwh[((size_t)(b * DI + d0 + d)) * LL + w * Hh + hc + h] = sbuf[h][w][d];
    }
}

// ================= K3: x_proj + dt projection + softplus (64-l tiles, 4 q-groups) =================
__global__ void __launch_bounds__(256) k3_xproj(const float* __restrict__ xpw,
                         const float* __restrict__ dtwg,
                         const float* __restrict__ dtbg)
{
    int lt = blockIdx.x % 36;
    int bk = blockIdx.x / 36;
    int k  = bk & 3;
    int b  = bk >> 2;
    int l0 = lt * 64;
    int tid = threadIdx.x;
    int ll = tid & 63, q = tid >> 6;

    __shared__ float xd[40][64];
    __shared__ float wp2[32][4][10];
    __shared__ float dtw[DI * Rr];

    const float* usrc = (((k & 1) == 0) ? g_xhw : g_xwh) + (size_t)b * DI * LL;
    bool rev = (k >= 2);
    int gl = rev ? (LL - 1 - (l0 + ll)) : (l0 + ll);

    for (int idx = tid; idx < DI * Rr; idx += 256)
        dtw[idx] = dtwg[(size_t)k * DI * Rr + idx];

    float acc[10];
    #pragma unroll
    for (int j = 0; j < 10; j++) acc[j] = 0.f;

    for (int dc = 0; dc < DI; dc += 32) {
        __syncthreads();
        for (int idx = tid; idx < 1280; idx += 256) {
            int c = idx >> 5, dd = idx & 31;
            wp2[dd][c & 3][c >> 2] = xpw[(size_t)(k * 40 + c) * DI + dc + dd];
        }
        __syncthreads();
        #pragma unroll
        for (int dd0 = 0; dd0 < 32; dd0 += 8) {
            float uv[8];
            #pragma unroll
            for (int i = 0; i < 8; i++)
                uv[i] = usrc[(size_t)(dc + dd0 + i) * LL + gl];
            #pragma unroll
            for (int i = 0; i < 8; i++) {
                const float* w = &wp2[dd0 + i][q][0];
                float u = uv[i];
                #pragma unroll
                for (int j = 0; j < 10; j++) acc[j] = fmaf(w[j], u, acc[j]);
            }
        }
    }
    __syncthreads();
    #pragma unroll
    for (int j = 0; j < 10; j++) xd[q + 4 * j][ll] = acc[j];
    __syncthreads();

    for (int idx = tid; idx < Nn * 64; idx += 256) {
        int nn = idx >> 6, li = idx & 63;
        g_Bm[((size_t)bk * Nn + nn) * LL + l0 + li] = xd[Rr + nn][li];
        g_Cm[((size_t)bk * Nn + nn) * LL + l0 + li] = xd[Rr + Nn + nn][li];
    }
    float dtr[8];
    #pragma unroll
    for (int r = 0; r < 8; r++) dtr[r] = xd[r][ll];

    const float* dtb = dtbg + k * DI;
    #pragma unroll 2
    for (int dd = 0; dd < 64; dd++) {
        int d = (q << 6) + dd;
        float4 w0 = *(const float4*)&dtw[d * 8];
        float4 w1 = *(const float4*)&dtw[d * 8 + 4];
        float a = dtb[d];
        a = fmaf(w0.x, dtr[0], a); a = fmaf(w0.y, dtr[1], a);
        a = fmaf(w0.z, dtr[2], a); a = fmaf(w0.w, dtr[3], a);
        a = fmaf(w1.x, dtr[4], a); a = fmaf(w1.y, dtr[5], a);
        a = fmaf(w1.z, dtr[6], a); a = fmaf(w1.w, dtr[7], a);
        float sp = fmaxf(a, 0.f) + __logf(1.f + __expf(-fabsf(a)));
        g_delta[((size_t)bk * DI + d) * LL + l0 + ll] = sp;
    }
}

// ================= K4: selective scan — smem-staged B/C, broadcast d/u prefetch =================
__global__ void __launch_bounds__(128) k4_scan(const float* __restrict__ A_logs,
                                               const float* __restrict__ Ds)
{
    int dg = blockIdx.x & 31;       // 32 d-groups of 8
    int bk = blockIdx.x >> 5;       // 0..15
    int k  = bk & 3;
    int b  = bk >> 2;
    int tid  = threadIdx.x;
    int lane = tid & 31;
    int warp = tid >> 5;
    int half = lane >> 4;
    int n    = lane & 15;
    int d    = dg * 8 + warp * 2 + half;

    float aa   = -expf(A_logs[((size_t)(k * DI + d)) * Nn + n]) * 1.44269504088896f;
    float Dv16 = Ds[k * DI + d] * 0.0625f;

    const float* dp = g_delta + ((size_t)bk * DI + d) * LL;
    const float* up = ((((k & 1) == 0) ? g_xhw : g_xwh)) + ((size_t)(b * DI + d)) * LL;
    const float* Bg = g_Bm + (size_t)bk * Nn * LL;
    const float* Cg = g_Cm + (size_t)bk * Nn * LL;
    const bool rev = (k >= 2);

    int ln4 = lane & 15;
    int vsel = (((ln4 >> 3) & 1) << 2) | (((ln4 >> 2) & 1) << 1) | ((ln4 >> 1) & 1);
    bool wlane = ((lane & 1) == 0);

    __shared__ float sB[Nn][65];
    __shared__ float sC[Nn][65];
    __shared__ float yb[4][2][64];

    // cooperative-load indices: 128 threads, 16 rows x 64 cols per stream
    int crow = tid >> 3;          // 0..15
    int ccol = (tid & 7) * 8;     // 0,8,...,56

    float h = 0.f;

#define LOADDU(T, Dq0,Dq1,Uq0,Uq1)                                             \
    {   int _t = (T);                                                          \
        Dq0 = *(const float4*)(dp + _t); Dq1 = *(const float4*)(dp + _t + 4);  \
        if (!rev) { Uq0 = *(const float4*)(up + _t); Uq1 = *(const float4*)(up + _t + 4); } \
        else {                                                                 \
            float4 p0 = *(const float4*)(up + (LL - 8 - _t));                  \
            float4 p1 = *(const float4*)(up + (LL - 4 - _t));                  \
            Uq0.x = p1.w; Uq0.y = p1.z; Uq0.z = p1.y; Uq0.w = p1.x;            \
            Uq1.x = p0.w; Uq1.y = p0.z; Uq1.z = p0.y; Uq1.w = p0.x; } }

    float4 D0, D1, U0, U1;
    LOADDU(0, D0, D1, U0, U1)

    for (int s0 = 0; s0 < LL; s0 += 64) {
        if (s0) __syncthreads();   // protect sB/sC from previous readers
        {
            float4 b0 = *(const float4*)(Bg + (size_t)crow * LL + s0 + ccol);
            float4 b1 = *(const float4*)(Bg + (size_t)crow * LL + s0 + ccol + 4);
            float4 c0 = *(const float4*)(Cg + (size_t)crow * LL + s0 + ccol);
            float4 c1 = *(const float4*)(Cg + (size_t)crow * LL + s0 + ccol + 4);
            sB[crow][ccol+0]=b0.x; sB[crow][ccol+1]=b0.y; sB[crow][ccol+2]=b0.z; sB[crow][ccol+3]=b0.w;
            sB[crow][ccol+4]=b1.x; sB[crow][ccol+5]=b1.y; sB[crow][ccol+6]=b1.z; sB[crow][ccol+7]=b1.w;
            sC[crow][ccol+0]=c0.x; sC[crow][ccol+1]=c0.y; sC[crow][ccol+2]=c0.z; sC[crow][ccol+3]=c0.w;
            sC[crow][ccol+4]=c1.x; sC[crow][ccol+5]=c1.y; sC[crow][ccol+6]=c1.z; sC[crow][ccol+7]=c1.w;
        }
        __syncthreads();

        #pragma unroll 2
        for (int c8 = 0; c8 < 64; c8 += 8) {
            int t0 = s0 + c8;
            float4 nD0 = D0, nD1 = D1, nU0 = U0, nU1 = U1;
            if (t0 + 8 < LL) LOADDU(t0 + 8, nD0, nD1, nU0, nU1)

            float dl[8] = {D0.x,D0.y,D0.z,D0.w,D1.x,D1.y,D1.z,D1.w};
            float uu[8] = {U0.x,U0.y,U0.z,U0.w,U1.x,U1.y,U1.z,U1.w};
            float bb[8], cc[8], ee[8], p[8];
            #pragma unroll
            for (int i = 0; i < 8; i++) { bb[i] = sB[n][c8 + i]; cc[i] = sC[n][c8 + i]; }
            #pragma unroll
            for (int i = 0; i < 8; i++) ee[i] = ex2f(dl[i] * aa);
            #pragma unroll
            for (int i = 0; i < 8; i++) {
                h = fmaf(h, ee[i], (dl[i] * uu[i]) * bb[i]);
                p[i] = fmaf(Dv16, uu[i], h * cc[i]);
            }
            #pragma unroll
            for (int i = 0; i < 8; i++) p[i] += __shfl_xor_sync(0xffffffffu, p[i], 8);
            float q0 = (lane & 8) ? p[4] : p[0];
            float q1 = (lane & 8) ? p[5] : p[1];
            float q2 = (lane & 8) ? p[6] : p[2];
            float q3 = (lane & 8) ? p[7] : p[3];
            q0 += __shfl_xor_sync(0xffffffffu, q0, 4);
            q1 += __shfl_xor_sync(0xffffffffu, q1, 4);
            q2 += __shfl_xor_sync(0xffffffffu, q2, 4);
            q3 += __shfl_xor_sync(0xffffffffu, q3, 4);
            float r0 = (lane & 4) ? q2 : q0;
            float r1 = (lane & 4) ? q3 : q1;
            r0 += __shfl_xor_sync(0xffffffffu, r0, 2);
            r1 += __shfl_xor_sync(0xffffffffu, r1, 2);
            float s = (lane & 2) ? r1 : r0;
            s += __shfl_xor_sync(0xffffffffu, s, 1);
            if (wlane) yb[warp][half][c8 + vsel] = s;

            D0 = nD0; D1 = nD1; U0 = nU0; U1 = nU1;
        }
        __syncwarp();
        {
            int idx = lane * 4, hs = idx >> 6, off = idx & 63;
            float4 v = *(float4*)&yb[warp][hs][off];
            *(float4*)(g_ys + ((size_t)bk * DI + dg * 8 + warp * 2 + hs) * LL + s0 + off) = v;
        }
        __syncwarp();
    }
#undef LOADDU
}

// ================= K5: combine the four direction outputs =================
__global__ void k5_combine()
{
    int hc = blockIdx.x % 6;
    int dc = (blockIdx.x / 6) & 15;
    int b  = blockIdx.x / 96;
    int d0 = dc * 16, h0 = hc * 8;
    __shared__ float s[16][392];
    int tid = threadIdx.x;
    const float* y0 = g_ys + ((size_t)(b * 4 + 0) * DI + d0) * LL;
    const float* y1 = g_ys + ((size_t)(b * 4 + 1) * DI + d0) * LL;
    const float* y2 = g_ys + ((size_t)(b * 4 + 2) * DI + d0) * LL;
    const float* y3 = g_ys + ((size_t)(b * 4 + 3) * DI + d0) * LL;
    int base = h0 * Ww;

    for (int idx = tid; idx < 16 * 384; idx += 256) {
        int d = idx / 384, p = idx % 384;
        int l = base + p;
        s[d][p] = y0[(size_t)d * LL + l] + y2[(size_t)d * LL + (LL - 1 - l)];
    }
    __syncthreads();
    for (int idx = tid; idx < 16 * 384; idx += 256) {
        int d = idx / 384, p = idx % 384;
        int w = p >> 3, hh = p & 7;
        int t1 = w * Hh + h0 + hh;
        float v = y1[(size_t)d * LL + t1] + y3[(size_t)d * LL + (LL - 1 - t1)];
        s[d][hh * Ww + w] += v;
    }
    __syncthreads();
    for (int idx = tid; idx < 384 * 16; idx += 256) {
        int p = idx >> 4, d = idx & 15;
        g_ycomb[((size_t)(b * LL + base + p)) * DI + d0 + d] = s[d][p];
    }
}

// ================= K6: LayerNorm(DI) + SiLU(z) gate =================
__global__ void k6_lngate(const float* __restrict__ og, const float* __restrict__ ob)
{
    int m = blockIdx.x;
    int tid = threadIdx.x;
    float v = g_ycomb[(size_t)m * DI + tid];
    float sm = v, sq = v * v;
    #pragma unroll
    for (int o = 16; o; o >>= 1) {
        sm += __shfl_xor_sync(0xffffffffu, sm, o);
        sq += __shfl_xor_sync(0xffffffffu, sq, o);
    }
    __shared__ float rs1[8], rs2[8];
    int w = tid >> 5, ln = tid & 31;
    if (ln == 0) { rs1[w] = sm; rs2[w] = sq; }
    __syncthreads();
    float ts = 0.f, tq = 0.f;
    #pragma unroll
    for (int i = 0; i < 8; i++) { ts += rs1[i]; tq += rs2[i]; }
    float mean = ts * (1.f / DI);
    float var  = tq * (1.f / DI) - mean * mean;
    float rstd = rsqrtf(var + 1e-5f);
    float zv = g_xz[(size_t)m * 512 + DI + tid];
    float gate = zv * sigmf(zv);
    g_yact[(size_t)m * DI + tid] = ((v - mean) * rstd * og[tid] + ob[tid]) * gate;
}

// ================= K7: out = x + (yact @ out_proj_w^T), (B,C,L) layout =================
__global__ void __launch_bounds__(256) k7_out(const float* __restrict__ Wout,
                                              const float* __restrict__ x,
                                              float* __restrict__ out)
{
    int b  = blockIdx.z;
    int c0 = blockIdx.x * 64;
    int l0 = blockIdx.y * 128;
    __shared__ float As[16][64];
    __shared__ float Bs[16][128];
    int tid = threadIdx.x;
    int tm = tid & 15, tn = tid >> 4;
    int arow = tid >> 2, akq = (tid & 3) * 4;
    int brow = tid >> 1, bkq = (tid & 1) * 8;
    float acc[4][8];
    #pragma unroll
    for (int i = 0; i < 4; i++)
        #pragma unroll
        for (int j = 0; j < 8; j++) acc[i][j] = 0.f;

    const float* Y = g_yact + (size_t)b * LL * DI;
    for (int k0 = 0; k0 < DI; k0 += 16) {
        float4 a0 = *(const float4*)(Wout + (size_t)(c0 + arow) * DI + k0 + akq);
        float4 b0 = *(const float4*)(Y + (size_t)(l0 + brow) * DI + k0 + bkq);
        float4 b1 = *(const float4*)(Y + (size_t)(l0 + brow) * DI + k0 + bkq + 4);
        __syncthreads();
        As[akq+0][arow]=a0.x; As[akq+1][arow]=a0.y; As[akq+2][arow]=a0.z; As[akq+3][arow]=a0.w;
        Bs[bkq+0][brow]=b0.x; Bs[bkq+1][brow]=b0.y; Bs[bkq+2][brow]=b0.z; Bs[bkq+3][brow]=b0.w;
        Bs[bkq+4][brow]=b1.x; Bs[bkq+5][brow]=b1.y; Bs[bkq+6][brow]=b1.z; Bs[bkq+7][brow]=b1.w;
        __syncthreads();
        #pragma unroll
        for (int kk = 0; kk < 16; kk++) {
            float4 av  = *(const float4*)&As[kk][tm << 2];
            float4 bv0 = *(const float4*)&Bs[kk][tn << 3];
            float4 bv1 = *(const float4*)&Bs[kk][(tn << 3) + 4];
            float am[4] = {av.x, av.y, av.z, av.w};
            float bn[8] = {bv0.x,bv0.y,bv0.z,bv0.w,bv1.x,bv1.y,bv1.z,bv1.w};
            #pragma unroll
            for (int i = 0; i < 4; i++)
                #pragma unroll
                for (int j = 0; j < 8; j++)
                    acc[i][j] = fmaf(am[i], bn[j], acc[i][j]);
        }
    }
    #pragma unroll
    for (int i = 0; i < 4; i++) {
        int c = c0 + (tm << 2) + i;
        size_t off = ((size_t)b * Cc + c) * LL + l0 + (tn << 3);
        float4 x0 = *(const float4*)(x + off);
        float4 x1 = *(const float4*)(x + off + 4);
        *(float4*)(out + off)     = make_float4(acc[i][0]+x0.x, acc[i][1]+x0.y, acc[i][2]+x0.z, acc[i][3]+x0.w);
        *(float4*)(out + off + 4) = make_float4(acc[i][4]+x1.x, acc[i][5]+x1.y, acc[i][6]+x1.z, acc[i][7]+x1.w);
    }
}

extern "C" void kernel_launch(void* const* d_in, const int* in_sizes, int n_in,
                              void* d_out, int out_size)
{
    const float* x          = (const float*)d_in[0];
    const float* ln1_g      = (const float*)d_in[1];
    const float* ln1_b      = (const float*)d_in[2];
    const float* in_proj_w  = (const float*)d_in[3];
    const float* conv_w     = (const float*)d_in[4];
    const float* conv_b     = (const float*)d_in[5];
    const float* x_proj_w   = (const float*)d_in[6];
    const float* dt_w       = (const float*)d_in[7];
    const float* dt_b       = (const float*)d_in[8];
    const float* A_logs     = (const float*)d_in[9];
    const float* Ds         = (const float*)d_in[10];
    const float* outn_g     = (const float*)d_in[11];
    const float* outn_b     = (const float*)d_in[12];
    const float* out_proj_w = (const float*)d_in[13];
    float* out = (float*)d_out;

    k0_ln<<<Bb * Hh, 256>>>(x, ln1_g, ln1_b);
    { dim3 g(BL / 128, 512 / 128); k1_gemm<<<g, 256>>>(in_proj_w); }
    k2_conv<<<Bb * 6 * 16, 256>>>(conv_w, conv_b);
    k3_xproj<<<Bb * Kk * 36, 256>>>(x_proj_w, dt_w, dt_b);
    k4_scan<<<32 * 16, 128>>>(A_logs, Ds);
    k5_combine<<<Bb * 16 * 6, 256>>>();
    k6_lngate<<<BL, 256>>>(outn_g, outn_b);
    { dim3 g(2, 18, Bb); k7_out<<<g, 256>>>(out_proj_w, x, out); }
}

// round 7
// speedup vs baseline: 1.9531x; 1.0171x over previous
#include <cuda_runtime.h>
#include <cuda_bf16.h>
#include <math.h>

#define Bb   4
#define Cc   128
#define DI   256
#define Nn   16
#define Rr   8
#define Kk   4
#define Hh   48
#define Ww   48
#define LL   2304
#define BL   9216

typedef unsigned long long u64t;
union F2U { u64t v; float s[2]; float2 f; };

__device__ __forceinline__ u64t pk2(float lo, float hi){
    u64t r; asm("mov.b64 %0, {%1, %2};" : "=l"(r) : "f"(lo), "f"(hi)); return r;
}
__device__ __forceinline__ u64t fma2(u64t a, u64t b, u64t c){
    u64t r; asm("fma.rn.f32x2 %0, %1, %2, %3;" : "=l"(r) : "l"(a), "l"(b), "l"(c)); return r;
}
__device__ __forceinline__ u64t mul2(u64t a, u64t b){
    u64t r; asm("mul.rn.f32x2 %0, %1, %2;" : "=l"(r) : "l"(a), "l"(b)); return r;
}
__device__ __forceinline__ u64t add2(u64t a, u64t b){
    u64t r; asm("add.rn.f32x2 %0, %1, %2;" : "=l"(r) : "l"(a), "l"(b)); return r;
}
__device__ __forceinline__ float ex2f(float x){
    float r; asm("ex2.approx.f32 %0, %1;" : "=f"(r) : "f"(x)); return r;
}
__device__ __forceinline__ float sigmf(float x){
    return 1.f / (1.f + __expf(-x));
}

// ---------------- scratch ----------------
__device__ float g_xn   [(size_t)BL * Cc];
__device__ float g_xz   [(size_t)BL * 2 * DI];
__device__ float g_xhw  [(size_t)Bb * DI * LL];
__device__ float g_xwh  [(size_t)Bb * DI * LL];
__device__ float g_delta[(size_t)Bb * Kk * DI * LL];
__device__ float g_Bm   [(size_t)Bb * Kk * Nn * LL];
__device__ float g_Cm   [(size_t)Bb * Kk * Nn * LL];
__device__ float g_ys   [(size_t)Bb * Kk * DI * LL];
__device__ float g_ycomb[(size_t)BL * DI];
__device__ float g_yact [(size_t)BL * DI];

// ================= K0: channel LayerNorm -> xn (B*L, C) =================
__global__ void k0_ln(const float* __restrict__ x,
                      const float* __restrict__ lg, const float* __restrict__ lb)
{
    int b = blockIdx.x / Hh;
    int h = blockIdx.x % Hh;
    __shared__ float s[Cc][Ww + 1];
    __shared__ float mu[Ww], rs[Ww];

    const float* xb = x + (size_t)b * Cc * LL + (size_t)h * Ww;
    for (int idx = threadIdx.x; idx < Cc * Ww; idx += 256) {
        int c = idx / Ww, w = idx % Ww;
        s[c][w] = xb[(size_t)c * LL + w];
    }
    __syncthreads();
    if (threadIdx.x < Ww) {
        int w = threadIdx.x;
        float sm = 0.f, sq = 0.f;
        #pragma unroll 8
        for (int c = 0; c < Cc; c++) { float v = s[c][w]; sm += v; sq += v * v; }
        float m = sm * (1.f / Cc);
        float var = sq * (1.f / Cc) - m * m;
        mu[w] = m; rs[w] = rsqrtf(var + 1e-5f);
    }
    __syncthreads();
    float* out = g_xn + ((size_t)(b * LL + h * Ww)) * Cc;
    for (int idx = threadIdx.x; idx < Ww * Cc; idx += 256) {
        int w = idx >> 7, c = idx & 127;
        out[idx] = (s[c][w] - mu[w]) * rs[w] * lg[c] + lb[c];
    }
}

// ================= K1: xz = xn @ in_proj_w^T (f32x2 micro) =================
__global__ void __launch_bounds__(256) k1_gemm(const float* __restrict__ Wp)
{
    __shared__ float As[16][128];
    __shared__ float Bs[16][128];
    int m0 = blockIdx.x * 128, n0 = blockIdx.y * 128;
    int tid = threadIdx.x;
    int tm = tid & 15, tn = tid >> 4;
    int row = tid >> 1, kq = (tid & 1) * 8;
    u64t acc2[8][4];
    #pragma unroll
    for (int i = 0; i < 8; i++)
        #pragma unroll
        for (int j = 0; j < 4; j++) acc2[i][j] = 0ULL;

    for (int k0 = 0; k0 < Cc; k0 += 16) {
        float4 a0 = *(const float4*)(g_xn + (size_t)(m0 + row) * Cc + k0 + kq);
        float4 a1 = *(const float4*)(g_xn + (size_t)(m0 + row) * Cc + k0 + kq + 4);
        float4 b0 = *(const float4*)(Wp   + (size_t)(n0 + row) * Cc + k0 + kq);
        float4 b1 = *(const float4*)(Wp   + (size_t)(n0 + row) * Cc + k0 + kq + 4);
        __syncthreads();
        As[kq+0][row]=a0.x; As[kq+1][row]=a0.y; As[kq+2][row]=a0.z; As[kq+3][row]=a0.w;
        As[kq+4][row]=a1.x; As[kq+5][row]=a1.y; As[kq+6][row]=a1.z; As[kq+7][row]=a1.w;
        Bs[kq+0][row]=b0.x; Bs[kq+1][row]=b0.y; Bs[kq+2][row]=b0.z; Bs[kq+3][row]=b0.w;
        Bs[kq+4][row]=b1.x; Bs[kq+5][row]=b1.y; Bs[kq+6][row]=b1.z; Bs[kq+7][row]=b1.w;
        __syncthreads();
        #pragma unroll
        for (int kk = 0; kk < 16; kk++) {
            float4 av0 = *(const float4*)&As[kk][tm << 3];
            float4 av1 = *(const float4*)&As[kk][(tm << 3) + 4];
            ulonglong2 bq0 = *(const ulonglong2*)&Bs[kk][tn << 3];
            ulonglong2 bq1 = *(const ulonglong2*)&Bs[kk][(tn << 3) + 4];
            u64t b2[4] = {bq0.x, bq0.y, bq1.x, bq1.y};
            float am[8] = {av0.x,av0.y,av0.z,av0.w,av1.x,av1.y,av1.z,av1.w};
            #pragma unroll
            for (int i = 0; i < 8; i++) {
                u64t a2 = pk2(am[i], am[i]);
                #pragma unroll
                for (int j = 0; j < 4; j++)
                    acc2[i][j] = fma2(a2, b2[j], acc2[i][j]);
            }
        }
    }
    #pragma unroll
    for (int i = 0; i < 8; i++) {
        float* o = g_xz + (size_t)(m0 + (tm << 3) + i) * 512 + n0 + (tn << 3);
        ulonglong2 s0 = make_ulonglong2(acc2[i][0], acc2[i][1]);
        ulonglong2 s1 = make_ulonglong2(acc2[i][2], acc2[i][3]);
        *(ulonglong2*)o       = s0;
        *(ulonglong2*)(o + 4) = s1;
    }
}

// ================= K2: depthwise conv3x3 + bias + SiLU -> x_hw, x_wh =================
__global__ void k2_conv(const float* __restrict__ cw, const float* __restrict__ cb)
{
    int bi  = blockIdx.x;
    int dci = bi & 15;
    int hci = (bi >> 4) % 6;
    int b   = bi / 96;
    int d0  = dci * 16;
    int hc  = hci * 8;
    int tid = threadIdx.x;

    __shared__ float sbuf[10][Ww][17];
    __shared__ float wgt[16][9];
    __shared__ float bia[16];

    if (tid < 144) wgt[tid / 9][tid % 9] = cw[(size_t)(d0 + tid / 9) * 9 + tid % 9];
    if (tid >= 144 && tid < 160) bia[tid - 144] = cb[d0 + tid - 144];

    for (int idx = tid; idx < 10 * Ww * 16; idx += 256) {
        int d = idx & 15;
        int rest = idx >> 4;
        int w = rest % Ww;
        int hh = rest / Ww;
        int gh = hc - 1 + hh;
        float v = 0.f;
        if (gh >= 0 && gh < Hh)
            v = g_xz[((size_t)(b * LL + gh * Ww + w)) * 512 + d0 + d];
        sbuf[hh][w][d] = v;
    }
    __syncthreads();

    float outv[24];
    #pragma unroll
    for (int it = 0; it < 24; it++) {
        int idx = tid + it * 256;
        int d = idx / 384;
        int r = idx % 384;
        int h = r / Ww;
        int w = r % Ww;
        float sum = bia[d];
        #pragma unroll
        for (int i = 0; i < 3; i++) {
            #pragma unroll
            for (int j = 0; j < 3; j++) {
                int ww = w + j - 1;
                float xv = (ww >= 0 && ww < Ww) ? sbuf[h + i][ww][d] : 0.f;
                sum = fmaf(wgt[d][i * 3 + j], xv, sum);
            }
        }
        outv[it] = sum * sigmf(sum);
    }
    __syncthreads();
    #pragma unroll
    for (int it = 0; it < 24; it++) {
        int idx = tid + it * 256;
        int d = idx / 384; int r = idx % 384; int h = r / Ww; int w = r % Ww;
        g_xhw[((size_t)(b * DI + d0 + d)) * LL + (hc + h) * Ww + w] = outv[it];
        sbuf[h][w][d] = outv[it];
    }
    __syncthreads();
    for (int it = 0; it < 24; it++) {
        int idx = tid + it * 256;
        int d = idx / 384; int r = idx % 384; int w = r >> 3; int h = r & 7;
        g_xwh[((size_t)(b * DI + d0 + d)) * LL + w * Hh + hc + h] = sbuf[h][w][d];
    }
}

// ================= K3: x_proj + dt projection + softplus (f32x2) =================
__global__ void __launch_bounds__(256) k3_xproj(const float* __restrict__ xpw,
                         const float* __restrict__ dtwg,
                         const float* __restrict__ dtbg)
{
    int lt = blockIdx.x % 36;
    int bk = blockIdx.x / 36;
    int k  = bk & 3;
    int b  = bk >> 2;
    int l0 = lt * 64;
    int tid = threadIdx.x;
    int ll = tid & 63, q = tid >> 6;

    __shared__ float xd[40][64];
    __shared__ float wp2[32][4][12];     // padded to 12 for 8B-aligned q-rows
    __shared__ float dtw[DI * Rr];

    const float* usrc = (((k & 1) == 0) ? g_xhw : g_xwh) + (size_t)b * DI * LL;
    bool rev = (k >= 2);
    int gl = rev ? (LL - 1 - (l0 + ll)) : (l0 + ll);

    for (int idx = tid; idx < DI * Rr; idx += 256)
        dtw[idx] = dtwg[(size_t)k * DI * Rr + idx];

    u64t acc2[5];
    #pragma unroll
    for (int j = 0; j < 5; j++) acc2[j] = 0ULL;

    for (int dc = 0; dc < DI; dc += 32) {
        __syncthreads();
        for (int idx = tid; idx < 1280; idx += 256) {
            int c = idx >> 5, dd = idx & 31;
            wp2[dd][c & 3][c >> 2] = xpw[(size_t)(k * 40 + c) * DI + dc + dd];
        }
        __syncthreads();
        #pragma unroll
        for (int dd0 = 0; dd0 < 32; dd0 += 8) {
            float uv[8];
            #pragma unroll
            for (int i = 0; i < 8; i++)
                uv[i] = usrc[(size_t)(dc + dd0 + i) * LL + gl];
            #pragma unroll
            for (int i = 0; i < 8; i++) {
                const u64t* w64 = (const u64t*)&wp2[dd0 + i][q][0];
                u64t u2 = pk2(uv[i], uv[i]);
                #pragma unroll
                for (int j = 0; j < 5; j++) acc2[j] = fma2(w64[j], u2, acc2[j]);
            }
        }
    }
    __syncthreads();
    #pragma unroll
    for (int j = 0; j < 5; j++) {
        F2U t; t.v = acc2[j];
        xd[q + 4 * (2 * j)][ll]     = t.s[0];
        xd[q + 4 * (2 * j + 1)][ll] = t.s[1];
    }
    __syncthreads();

    for (int idx = tid; idx < Nn * 64; idx += 256) {
        int nn = idx >> 6, li = idx & 63;
        g_Bm[((size_t)bk * Nn + nn) * LL + l0 + li] = xd[Rr + nn][li];
        g_Cm[((size_t)bk * Nn + nn) * LL + l0 + li] = xd[Rr + Nn + nn][li];
    }
    u64t dtr2[4];
    #pragma unroll
    for (int r = 0; r < 4; r++) dtr2[r] = pk2(xd[2 * r][ll], xd[2 * r + 1][ll]);

    const float* dtb = dtbg + k * DI;
    #pragma unroll 2
    for (int dd = 0; dd < 64; dd++) {
        int d = (q << 6) + dd;
        ulonglong2 wq0 = *(const ulonglong2*)&dtw[d * 8];
        ulonglong2 wq1 = *(const ulonglong2*)&dtw[d * 8 + 4];
        u64t m = fma2(wq0.x, dtr2[0],
                  fma2(wq0.y, dtr2[1],
                   fma2(wq1.x, dtr2[2],
                    mul2(wq1.y, dtr2[3]))));
        F2U t; t.v = m;
        float a = dtb[d] + t.s[0] + t.s[1];
        float sp = fmaxf(a, 0.f) + __logf(1.f + __expf(-fabsf(a)));
        g_delta[((size_t)bk * DI + d) * LL + l0 + ll] = sp;
    }
}

// ================= K4: selective scan — smem B/C (LDS.64), f32x2, no D-term =================
__global__ void __launch_bounds__(128) k4_scan(const float* __restrict__ A_logs)
{
    int dg = blockIdx.x & 31;
    int bk = blockIdx.x >> 5;
    int k  = bk & 3;
    int b  = bk >> 2;
    int tid  = threadIdx.x;
    int lane = tid & 31;
    int warp = tid >> 5;
    int half = lane >> 4;
    int n    = lane & 15;
    int d    = dg * 8 + warp * 2 + half;

    float aa = -expf(A_logs[((size_t)(k * DI + d)) * Nn + n]) * 1.44269504088896f;
    u64t aa2 = pk2(aa, aa);

    const float* dp = g_delta + ((size_t)bk * DI + d) * LL;
    const float* up = ((((k & 1) == 0) ? g_xhw : g_xwh)) + ((size_t)(b * DI + d)) * LL;
    const float* Bg = g_Bm + (size_t)bk * Nn * LL;
    const float* Cg = g_Cm + (size_t)bk * Nn * LL;
    const bool rev = (k >= 2);

    int ln4 = lane & 15;
    int vsel = (((ln4 >> 3) & 1) << 2) | (((ln4 >> 2) & 1) << 1) | ((ln4 >> 1) & 1);
    bool wlane = ((lane & 1) == 0);

    __shared__ float sB[Nn][66];
    __shared__ float sC[Nn][66];
    __shared__ float yb[4][2][64];

    int crow = tid >> 3;
    int ccol = (tid & 7) * 8;

    float h = 0.f;

#define LOADDU(T, Dq0,Dq1,Uq0,Uq1)                                             \
    {   int _t = (T);                                                          \
        Dq0 = *(const float4*)(dp + _t); Dq1 = *(const float4*)(dp + _t + 4);  \
        if (!rev) { Uq0 = *(const float4*)(up + _t); Uq1 = *(const float4*)(up + _t + 4); } \
        else {                                                                 \
            float4 p0 = *(const float4*)(up + (LL - 8 - _t));                  \
            float4 p1 = *(const float4*)(up + (LL - 4 - _t));                  \
            Uq0.x = p1.w; Uq0.y = p1.z; Uq0.z = p1.y; Uq0.w = p1.x;            \
            Uq1.x = p0.w; Uq1.y = p0.z; Uq1.z = p0.y; Uq1.w = p0.x; } }

    float4 D0, D1, U0, U1;
    LOADDU(0, D0, D1, U0, U1)

    for (int s0 = 0; s0 < LL; s0 += 64) {
        if (s0) __syncthreads();
        {
            float4 b0 = *(const float4*)(Bg + (size_t)crow * LL + s0 + ccol);
            float4 b1 = *(const float4*)(Bg + (size_t)crow * LL + s0 + ccol + 4);
            float4 c0 = *(const float4*)(Cg + (size_t)crow * LL + s0 + ccol);
            float4 c1 = *(const float4*)(Cg + (size_t)crow * LL + s0 + ccol + 4);
            float2* db = (float2*)&sB[crow][0];
            float2* dc = (float2*)&sC[crow][0];
            int p0 = ccol >> 1;
            db[p0+0] = make_float2(b0.x, b0.y); db[p0+1] = make_float2(b0.z, b0.w);
            db[p0+2] = make_float2(b1.x, b1.y); db[p0+3] = make_float2(b1.z, b1.w);
            dc[p0+0] = make_float2(c0.x, c0.y); dc[p0+1] = make_float2(c0.z, c0.w);
            dc[p0+2] = make_float2(c1.x, c1.y); dc[p0+3] = make_float2(c1.z, c1.w);
        }
        __syncthreads();

        #pragma unroll 2
        for (int c8 = 0; c8 < 64; c8 += 8) {
            int t0 = s0 + c8;
            float4 nD0 = D0, nD1 = D1, nU0 = U0, nU1 = U1;
            if (t0 + 8 < LL) LOADDU(t0 + 8, nD0, nD1, nU0, nU1)

            F2U dl2[4], uu2[4];
            dl2[0].f = make_float2(D0.x, D0.y); dl2[1].f = make_float2(D0.z, D0.w);
            dl2[2].f = make_float2(D1.x, D1.y); dl2[3].f = make_float2(D1.z, D1.w);
            uu2[0].f = make_float2(U0.x, U0.y); uu2[1].f = make_float2(U0.z, U0.w);
            uu2[2].f = make_float2(U1.x, U1.y); uu2[3].f = make_float2(U1.z, U1.w);

            const u64t* b64 = (const u64t*)&sB[n][0];
            const u64t* c64 = (const u64t*)&sC[n][0];
            int pb = c8 >> 1;

            F2U ee[4], gg[4], cc[4];
            #pragma unroll
            for (int j = 0; j < 4; j++) {
                ee[j].v = mul2(dl2[j].v, aa2);
                gg[j].v = mul2(mul2(dl2[j].v, uu2[j].v), b64[pb + j]);
                cc[j].v = c64[pb + j];
            }
            float p[8];
            #pragma unroll
            for (int j = 0; j < 4; j++) {
                float e0 = ex2f(ee[j].s[0]);
                float e1 = ex2f(ee[j].s[1]);
                h = fmaf(h, e0, gg[j].s[0]);
                p[2*j]   = h * cc[j].s[0];
                h = fmaf(h, e1, gg[j].s[1]);
                p[2*j+1] = h * cc[j].s[1];
            }
            #pragma unroll
            for (int i = 0; i < 8; i++) p[i] += __shfl_xor_sync(0xffffffffu, p[i], 8);
            float q0 = (lane & 8) ? p[4] : p[0];
            float q1 = (lane & 8) ? p[5] : p[1];
            float q2 = (lane & 8) ? p[6] : p[2];
            float q3 = (lane & 8) ? p[7] : p[3];
            q0 += __shfl_xor_sync(0xffffffffu, q0, 4);
            q1 += __shfl_xor_sync(0xffffffffu, q1, 4);
            q2 += __shfl_xor_sync(0xffffffffu, q2, 4);
            q3 += __shfl_xor_sync(0xffffffffu, q3, 4);
            float r0 = (lane & 4) ? q2 : q0;
            float r1 = (lane & 4) ? q3 : q1;
            r0 += __shfl_xor_sync(0xffffffffu, r0, 2);
            r1 += __shfl_xor_sync(0xffffffffu, r1, 2);
            float s = (lane & 2) ? r1 : r0;
            s += __shfl_xor_sync(0xffffffffu, s, 1);
            if (wlane) yb[warp][half][c8 + vsel] = s;

            D0 = nD0; D1 = nD1; U0 = nU0; U1 = nU1;
        }
        __syncwarp();
        {
            int idx = lane * 4, hs = idx >> 6, off = idx & 63;
            float4 v = *(float4*)&yb[warp][hs][off];
            *(float4*)(g_ys + ((size_t)bk * DI + dg * 8 + warp * 2 + hs) * LL + s0 + off) = v;
        }
        __syncwarp();
    }
#undef LOADDU
}

// ================= K5: combine 4 directions + D*u terms =================
__global__ void k5_combine(const float* __restrict__ Ds)
{
    int hc = blockIdx.x % 6;
    int dc = (blockIdx.x / 6) & 15;
    int b  = blockIdx.x / 96;
    int d0 = dc * 16, h0 = hc * 8;
    __shared__ float s[16][392];
    __shared__ float sD02[16], sD13[16];
    int tid = threadIdx.x;
    const float* y0 = g_ys + ((size_t)(b * 4 + 0) * DI + d0) * LL;
    const float* y1 = g_ys + ((size_t)(b * 4 + 1) * DI + d0) * LL;
    const float* y2 = g_ys + ((size_t)(b * 4 + 2) * DI + d0) * LL;
    const float* y3 = g_ys + ((size_t)(b * 4 + 3) * DI + d0) * LL;
    const float* xh = g_xhw + ((size_t)(b * DI + d0)) * LL;
    const float* xw = g_xwh + ((size_t)(b * DI + d0)) * LL;
    int base = h0 * Ww;

    if (tid < 16) {
        sD02[tid] = Ds[0 * DI + d0 + tid] + Ds[2 * DI + d0 + tid];
        sD13[tid] = Ds[1 * DI + d0 + tid] + Ds[3 * DI + d0 + tid];
    }
    __syncthreads();

    for (int idx = tid; idx < 16 * 384; idx += 256) {
        int d = idx / 384, p = idx % 384;
        int l = base + p;
        s[d][p] = y0[(size_t)d * LL + l] + y2[(size_t)d * LL + (LL - 1 - l)]
                + sD02[d] * xh[(size_t)d * LL + l];
    }
    __syncthreads();
    for (int idx = tid; idx < 16 * 384; idx += 256) {
        int d = idx / 384, p = idx % 384;
        int w = p >> 3, hh = p & 7;
        int t1 = w * Hh + h0 + hh;
        float v = y1[(size_t)d * LL + t1] + y3[(size_t)d * LL + (LL - 1 - t1)]
                + sD13[d] * xw[(size_t)d * LL + t1];
        s[d][hh * Ww + w] += v;
    }
    __syncthreads();
    for (int idx = tid; idx < 384 * 16; idx += 256) {
        int p = idx >> 4, d = idx & 15;
        g_ycomb[((size_t)(b * LL + base + p)) * DI + d0 + d] = s[d][p];
    }
}

// ================= K6: LayerNorm(DI) + SiLU(z) gate =================
__global__ void k6_lngate(const float* __restrict__ og, const float* __restrict__ ob)
{
    int m = blockIdx.x;
    int tid = threadIdx.x;
    float v = g_ycomb[(size_t)m * DI + tid];
    float sm = v, sq = v * v;
    #pragma unroll
    for (int o = 16; o; o >>= 1) {
        sm += __shfl_xor_sync(0xffffffffu, sm, o);
        sq += __shfl_xor_sync(0xffffffffu, sq, o);
    }
    __shared__ float rs1[8], rs2[8];
    int w = tid >> 5, ln = tid & 31;
    if (ln == 0) { rs1[w] = sm; rs2[w] = sq; }
    __syncthreads();
    float ts = 0.f, tq = 0.f;
    #pragma unroll
    for (int i = 0; i < 8; i++) { ts += rs1[i]; tq += rs2[i]; }
    float mean = ts * (1.f / DI);
    float var  = tq * (1.f / DI) - mean * mean;
    float rstd = rsqrtf(var + 1e-5f);
    float zv = g_xz[(size_t)m * 512 + DI + tid];
    float gate = zv * sigmf(zv);
    g_yact[(size_t)m * DI + tid] = ((v - mean) * rstd * og[tid] + ob[tid]) * gate;
}

// ================= K7: out = x + (yact @ out_proj_w^T) (f32x2) =================
__global__ void __launch_bounds__(256) k7_out(const float* __restrict__ Wout,
                                              const float* __restrict__ x,
                                              float* __restrict__ out)
{
    int b  = blockIdx.z;
    int c0 = blockIdx.x * 64;
    int l0 = blockIdx.y * 128;
    __shared__ float As[16][64];
    __shared__ float Bs[16][128];
    int tid = threadIdx.x;
    int tm = tid & 15, tn = tid >> 4;
    int arow = tid >> 2, akq = (tid & 3) * 4;
    int brow = tid >> 1, bkq = (tid & 1) * 8;
    u64t acc2[4][4];
    #pragma unroll
    for (int i = 0; i < 4; i++)
        #pragma unroll
        for (int j = 0; j < 4; j++) acc2[i][j] = 0ULL;

    const float* Y = g_yact + (size_t)b * LL * DI;
    for (int k0 = 0; k0 < DI; k0 += 16) {
        float4 a0 = *(const float4*)(Wout + (size_t)(c0 + arow) * DI + k0 + akq);
        float4 b0 = *(const float4*)(Y + (size_t)(l0 + brow) * DI + k0 + bkq);
        float4 b1 = *(const float4*)(Y + (size_t)(l0 + brow) * DI + k0 + bkq + 4);
        __syncthreads();
        As[akq+0][arow]=a0.x; As[akq+1][arow]=a0.y; As[akq+2][arow]=a0.z; As[akq+3][arow]=a0.w;
        Bs[bkq+0][brow]=b0.x; Bs[bkq+1][brow]=b0.y; Bs[bkq+2][brow]=b0.z; Bs[bkq+3][brow]=b0.w;
        Bs[bkq+4][brow]=b1.x; Bs[bkq+5][brow]=b1.y; Bs[bkq+6][brow]=b1.z; Bs[bkq+7][brow]=b1.w;
        __syncthreads();
        #pragma unroll
        for (int kk = 0; kk < 16; kk++) {
            float4 av  = *(const float4*)&As[kk][tm << 2];
            ulonglong2 bq0 = *(const ulonglong2*)&Bs[kk][tn << 3];
            ulonglong2 bq1 = *(const ulonglong2*)&Bs[kk][(tn << 3) + 4];
            u64t b2[4] = {bq0.x, bq0.y, bq1.x, bq1.y};
            float am[4] = {av.x, av.y, av.z, av.w};
            #pragma unroll
            for (int i = 0; i < 4; i++) {
                u64t a2 = pk2(am[i], am[i]);
                #pragma unroll
                for (int j = 0; j < 4; j++)
                    acc2[i][j] = fma2(a2, b2[j], acc2[i][j]);
            }
        }
    }
    #pragma unroll
    for (int i = 0; i < 4; i++) {
        int c = c0 + (tm << 2) + i;
        size_t off = ((size_t)b * Cc + c) * LL + l0 + (tn << 3);
        ulonglong2 x0 = *(const ulonglong2*)(x + off);
        ulonglong2 x1 = *(const ulonglong2*)(x + off + 4);
        ulonglong2 s0 = make_ulonglong2(add2(acc2[i][0], x0.x), add2(acc2[i][1], x0.y));
        ulonglong2 s1 = make_ulonglong2(add2(acc2[i][2], x1.x), add2(acc2[i][3], x1.y));
        *(ulonglong2*)(out + off)     = s0;
        *(ulonglong2*)(out + off + 4) = s1;
    }
}

extern "C" void kernel_launch(void* const* d_in, const int* in_sizes, int n_in,
                              void* d_out, int out_size)
{
    const float* x          = (const float*)d_in[0];
    const float* ln1_g      = (const float*)d_in[1];
    const float* ln1_b      = (const float*)d_in[2];
    const float* in_proj_w  = (const float*)d_in[3];
    const float* conv_w     = (const float*)d_in[4];
    const float* conv_b     = (const float*)d_in[5];
    const float* x_proj_w   = (const float*)d_in[6];
    const float* dt_w       = (const float*)d_in[7];
    const float* dt_b       = (const float*)d_in[8];
    const float* A_logs     = (const float*)d_in[9];
    const float* Ds         = (const float*)d_in[10];
    const float* outn_g     = (const float*)d_in[11];
    const float* outn_b     = (const float*)d_in[12];
    const float* out_proj_w = (const float*)d_in[13];
    float* out = (float*)d_out;

    k0_ln<<<Bb * Hh, 256>>>(x, ln1_g, ln1_b);
    { dim3 g(BL / 128, 512 / 128); k1_gemm<<<g, 256>>>(in_proj_w); }
    k2_conv<<<Bb * 6 * 16, 256>>>(conv_w, conv_b);
    k3_xproj<<<Bb * Kk * 36, 256>>>(x_proj_w, dt_w, dt_b);
    k4_scan<<<32 * 16, 128>>>(A_logs);
    k5_combine<<<Bb * 16 * 6, 256>>>(Ds);
    k6_lngate<<<BL, 256>>>(outn_g, outn_b);
    { dim3 g(2, 18, Bb); k7_out<<<g, 256>>>(out_proj_w, x, out); }
}

// round 8
// speedup vs baseline: 1.9621x; 1.0046x over previous
#include <cuda_runtime.h>
#include <cuda_bf16.h>
#include <math.h>

#define Bb   4
#define Cc   128
#define DI   256
#define Nn   16
#define Rr   8
#define Kk   4
#define Hh   48
#define Ww   48
#define LL   2304
#define BL   9216

typedef unsigned long long u64t;
union F2U { u64t v; float s[2]; float2 f; };

__device__ __forceinline__ u64t pk2(float lo, float hi){
    u64t r; asm("mov.b64 %0, {%1, %2};" : "=l"(r) : "f"(lo), "f"(hi)); return r;
}
__device__ __forceinline__ u64t fma2(u64t a, u64t b, u64t c){
    u64t r; asm("fma.rn.f32x2 %0, %1, %2, %3;" : "=l"(r) : "l"(a), "l"(b), "l"(c)); return r;
}
__device__ __forceinline__ u64t mul2(u64t a, u64t b){
    u64t r; asm("mul.rn.f32x2 %0, %1, %2;" : "=l"(r) : "l"(a), "l"(b)); return r;
}
__device__ __forceinline__ u64t add2(u64t a, u64t b){
    u64t r; asm("add.rn.f32x2 %0, %1, %2;" : "=l"(r) : "l"(a), "l"(b)); return r;
}
__device__ __forceinline__ float ex2f(float x){
    float r; asm("ex2.approx.f32 %0, %1;" : "=f"(r) : "f"(x)); return r;
}
__device__ __forceinline__ float sigmf(float x){
    return 1.f / (1.f + __expf(-x));
}

// ---------------- scratch ----------------
__device__ float g_xn   [(size_t)BL * Cc];
__device__ float g_xz   [(size_t)BL * 2 * DI];
__device__ float g_xhw  [(size_t)Bb * DI * LL];
__device__ float g_xwh  [(size_t)Bb * DI * LL];
__device__ float g_delta[(size_t)Bb * Kk * DI * LL];
__device__ float g_Bm   [(size_t)Bb * Kk * Nn * LL];
__device__ float g_Cm   [(size_t)Bb * Kk * Nn * LL];
__device__ float g_ys   [(size_t)Bb * Kk * DI * LL];
__device__ float g_ycomb[(size_t)BL * DI];
__device__ float g_yact [(size_t)BL * DI];

// ================= K0: channel LayerNorm -> xn (B*L, C) =================
__global__ void k0_ln(const float* __restrict__ x,
                      const float* __restrict__ lg, const float* __restrict__ lb)
{
    int b = blockIdx.x / Hh;
    int h = blockIdx.x % Hh;
    __shared__ float s[Cc][Ww + 1];
    __shared__ float mu[Ww], rs[Ww];

    const float* xb = x + (size_t)b * Cc * LL + (size_t)h * Ww;
    for (int idx = threadIdx.x; idx < Cc * Ww; idx += 256) {
        int c = idx / Ww, w = idx % Ww;
        s[c][w] = xb[(size_t)c * LL + w];
    }
    __syncthreads();
    if (threadIdx.x < Ww) {
        int w = threadIdx.x;
        float sm = 0.f, sq = 0.f;
        #pragma unroll 8
        for (int c = 0; c < Cc; c++) { float v = s[c][w]; sm += v; sq += v * v; }
        float m = sm * (1.f / Cc);
        float var = sq * (1.f / Cc) - m * m;
        mu[w] = m; rs[w] = rsqrtf(var + 1e-5f);
    }
    __syncthreads();
    float* out = g_xn + ((size_t)(b * LL + h * Ww)) * Cc;
    for (int idx = threadIdx.x; idx < Ww * Cc; idx += 256) {
        int w = idx >> 7, c = idx & 127;
        out[idx] = (s[c][w] - mu[w]) * rs[w] * lg[c] + lb[c];
    }
}

// ================= K1: xz = xn @ in_proj_w^T (f32x2 micro) =================
__global__ void __launch_bounds__(256) k1_gemm(const float* __restrict__ Wp)
{
    __shared__ float As[16][128];
    __shared__ float Bs[16][128];
    int m0 = blockIdx.x * 128, n0 = blockIdx.y * 128;
    int tid = threadIdx.x;
    int tm = tid & 15, tn = tid >> 4;
    int row = tid >> 1, kq = (tid & 1) * 8;
    u64t acc2[8][4];
    #pragma unroll
    for (int i = 0; i < 8; i++)
        #pragma unroll
        for (int j = 0; j < 4; j++) acc2[i][j] = 0ULL;

    for (int k0 = 0; k0 < Cc; k0 += 16) {
        float4 a0 = *(const float4*)(g_xn + (size_t)(m0 + row) * Cc + k0 + kq);
        float4 a1 = *(const float4*)(g_xn + (size_t)(m0 + row) * Cc + k0 + kq + 4);
        float4 b0 = *(const float4*)(Wp   + (size_t)(n0 + row) * Cc + k0 + kq);
        float4 b1 = *(const float4*)(Wp   + (size_t)(n0 + row) * Cc + k0 + kq + 4);
        __syncthreads();
        As[kq+0][row]=a0.x; As[kq+1][row]=a0.y; As[kq+2][row]=a0.z; As[kq+3][row]=a0.w;
        As[kq+4][row]=a1.x; As[kq+5][row]=a1.y; As[kq+6][row]=a1.z; As[kq+7][row]=a1.w;
        Bs[kq+0][row]=b0.x; Bs[kq+1][row]=b0.y; Bs[kq+2][row]=b0.z; Bs[kq+3][row]=b0.w;
        Bs[kq+4][row]=b1.x; Bs[kq+5][row]=b1.y; Bs[kq+6][row]=b1.z; Bs[kq+7][row]=b1.w;
        __syncthreads();
        #pragma unroll
        for (int kk = 0; kk < 16; kk++) {
            float4 av0 = *(const float4*)&As[kk][tm << 3];
            float4 av1 = *(const float4*)&As[kk][(tm << 3) + 4];
            ulonglong2 bq0 = *(const ulonglong2*)&Bs[kk][tn << 3];
            ulonglong2 bq1 = *(const ulonglong2*)&Bs[kk][(tn << 3) + 4];
            u64t b2[4] = {bq0.x, bq0.y, bq1.x, bq1.y};
            float am[8] = {av0.x,av0.y,av0.z,av0.w,av1.x,av1.y,av1.z,av1.w};
            #pragma unroll
            for (int i = 0; i < 8; i++) {
                u64t a2 = pk2(am[i], am[i]);
                #pragma unroll
                for (int j = 0; j < 4; j++)
                    acc2[i][j] = fma2(a2, b2[j], acc2[i][j]);
            }
        }
    }
    #pragma unroll
    for (int i = 0; i < 8; i++) {
        float* o = g_xz + (size_t)(m0 + (tm << 3) + i) * 512 + n0 + (tn << 3);
        ulonglong2 s0 = make_ulonglong2(acc2[i][0], acc2[i][1]);
        ulonglong2 s1 = make_ulonglong2(acc2[i][2], acc2[i][3]);
        *(ulonglong2*)o       = s0;
        *(ulonglong2*)(o + 4) = s1;
    }
}

// ================= K2: depthwise conv3x3 + bias + SiLU -> x_hw, x_wh =================
__global__ void k2_conv(const float* __restrict__ cw, const float* __restrict__ cb)
{
    int bi  = blockIdx.x;
    int dci = bi & 15;
    int hci = (bi >> 4) % 6;
    int b   = bi / 96;
    int d0  = dci * 16;
    int hc  = hci * 8;
    int tid = threadIdx.x;

    __shared__ float sbuf[10][Ww][17];
    __shared__ float wgt[16][9];
    __shared__ float bia[16];

    if (tid < 144) wgt[tid / 9][tid % 9] = cw[(size_t)(d0 + tid / 9) * 9 + tid % 9];
    if (tid >= 144 && tid < 160) bia[tid - 144] = cb[d0 + tid - 144];

    for (int idx = tid; idx < 10 * Ww * 16; idx += 256) {
        int d = idx & 15;
        int rest = idx >> 4;
        int w = rest % Ww;
        int hh = rest / Ww;
        int gh = hc - 1 + hh;
        float v = 0.f;
        if (gh >= 0 && gh < Hh)
            v = g_xz[((size_t)(b * LL + gh * Ww + w)) * 512 + d0 + d];
        sbuf[hh][w][d] = v;
    }
    __syncthreads();

    float outv[24];
    #pragma unroll
    for (int it = 0; it < 24; it++) {
        int idx = tid + it * 256;
        int d = idx / 384;
        int r = idx % 384;
        int h = r / Ww;
        int w = r % Ww;
        float sum = bia[d];
        #pragma unroll
        for (int i = 0; i < 3; i++) {
            #pragma unroll
            for (int j = 0; j < 3; j++) {
                int ww = w + j - 1;
                float xv = (ww >= 0 && ww < Ww) ? sbuf[h + i][ww][d] : 0.f;
                sum = fmaf(wgt[d][i * 3 + j], xv, sum);
            }
        }
        outv[it] = sum * sigmf(sum);
    }
    __syncthreads();
    #pragma unroll
    for (int it = 0; it < 24; it++) {
        int idx = tid + it * 256;
        int d = idx / 384; int r = idx % 384; int h = r / Ww; int w = r % Ww;
        g_xhw[((size_t)(b * DI + d0 + d)) * LL + (hc + h) * Ww + w] = outv[it];
        sbuf[h][w][d] = outv[it];
    }
    __syncthreads();
    for (int it = 0; it < 24; it++) {
        int idx = tid + it * 256;
        int d = idx / 384; int r = idx % 384; int w = r >> 3; int h = r & 7;
        g_xwh[((size_t)(b * DI + d0 + d)) * LL + w * Hh + hc + h] = sbuf[h][w][d];
    }
}

// ================= K3: x_proj + dt + softplus — register-tiled GEMM (2l x 10c) =================
// smem layout (floats): [0,5280): uT[32][132] (GEMM) overlaid by xd[40][130] (epilogue)
//                       [5280,6816): wp[32][4][12]   [6816,8864): dtw[2048]
__global__ void __launch_bounds__(256) k3_xproj(const float* __restrict__ xpw,
                         const float* __restrict__ dtwg,
                         const float* __restrict__ dtbg)
{
    __shared__ float sm[8864];
    float* uT  = sm;
    float* xd  = sm;
    float* wp  = sm + 5280;
    float* dtw = sm + 6816;

    int lt = blockIdx.x % 18;
    int bk = blockIdx.x / 18;
    int k  = bk & 3;
    int b  = bk >> 2;
    int l0 = lt * 128;
    int tid = threadIdx.x;

    const float* usrc = (((k & 1) == 0) ? g_xhw : g_xwh) + (size_t)b * DI * LL;
    const bool rev = (k >= 2);

    for (int idx = tid; idx < DI * Rr; idx += 256)
        dtw[idx] = dtwg[(size_t)k * DI * Rr + idx];

    int lg = tid & 63;     // 2 l's per thread: l = lg*2, lg*2+1
    int cg = tid >> 6;     // 0..3; c = cg + 4*j

    u64t acc2[2][5];
    #pragma unroll
    for (int li = 0; li < 2; li++)
        #pragma unroll
        for (int jp = 0; jp < 5; jp++) acc2[li][jp] = 0ULL;

    int srow = tid >> 3;          // 0..31 (dd row)
    int scol = (tid & 7) * 16;    // 16 floats each

    for (int dc = 0; dc < DI; dc += 32) {
        __syncthreads();
        // stage weights: wp[dd][c&3][c>>2]
        for (int idx = tid; idx < 1280; idx += 256) {
            int c = idx >> 5, dd = idx & 31;
            wp[dd * 48 + (c & 3) * 12 + (c >> 2)] = xpw[(size_t)(k * 40 + c) * DI + dc + dd];
        }
        // stage u tile (reversal folded in)
        {
            const float* urow = usrc + (size_t)(dc + srow) * LL;
            float* ud = uT + srow * 132;
            if (!rev) {
                #pragma unroll
                for (int m = 0; m < 4; m++) {
                    float4 v = *(const float4*)(urow + l0 + scol + m * 4);
                    *(float4*)(ud + scol + m * 4) = v;
                }
            } else {
                #pragma unroll
                for (int m = 0; m < 4; m++) {
                    int c4 = scol + m * 4;
                    float4 v = *(const float4*)(urow + (LL - 4 - l0 - c4));
                    *(float4*)(ud + c4) = make_float4(v.w, v.z, v.y, v.x);
                }
            }
        }
        __syncthreads();
        #pragma unroll 4
        for (int dd = 0; dd < 32; dd++) {
            F2U u2; u2.v = *(const u64t*)(uT + dd * 132 + lg * 2);
            u64t ua = pk2(u2.s[0], u2.s[0]);
            u64t ub = pk2(u2.s[1], u2.s[1]);
            const u64t* w64 = (const u64t*)(wp + dd * 48 + cg * 12);
            #pragma unroll
            for (int jp = 0; jp < 5; jp++) {
                u64t w2 = w64[jp];
                acc2[0][jp] = fma2(ua, w2, acc2[0][jp]);
                acc2[1][jp] = fma2(ub, w2, acc2[1][jp]);
            }
        }
    }
    __syncthreads();
    // spill results to xd[40][130]; pair (jp) covers c = cg+8jp and cg+8jp+4
    #pragma unroll
    for (int jp = 0; jp < 5; jp++)
        #pragma unroll
        for (int li = 0; li < 2; li++) {
            F2U t; t.v = acc2[li][jp];
            xd[(cg + 8 * jp) * 130 + lg * 2 + li]     = t.s[0];
            xd[(cg + 8 * jp + 4) * 130 + lg * 2 + li] = t.s[1];
        }
    __syncthreads();

    // B / C rows out (scan-order layout)
    for (int idx = tid; idx < Nn * 128; idx += 256) {
        int nn = idx >> 7, li = idx & 127;
        g_Bm[((size_t)bk * Nn + nn) * LL + l0 + li] = xd[(Rr + nn) * 130 + li];
        g_Cm[((size_t)bk * Nn + nn) * LL + l0 + li] = xd[(Rr + Nn + nn) * 130 + li];
    }

    // delta = softplus(dts @ dtw^T + dtb)
    int l = tid & 127, q = tid >> 7;
    u64t dtr2[4];
    #pragma unroll
    for (int r = 0; r < 4; r++)
        dtr2[r] = pk2(xd[(2 * r) * 130 + l], xd[(2 * r + 1) * 130 + l]);

    const float* dtb = dtbg + k * DI;
    #pragma unroll 2
    for (int dd = 0; dd < 128; dd++) {
        int d = (q << 7) + dd;
        ulonglong2 wq0 = *(const ulonglong2*)(dtw + d * 8);
        ulonglong2 wq1 = *(const ulonglong2*)(dtw + d * 8 + 4);
        u64t m = fma2(wq0.x, dtr2[0],
                  fma2(wq0.y, dtr2[1],
                   fma2(wq1.x, dtr2[2],
                    mul2(wq1.y, dtr2[3]))));
        F2U t; t.v = m;
        float a = dtb[d] + t.s[0] + t.s[1];
        float sp = fmaxf(a, 0.f) + __logf(1.f + __expf(-fabsf(a)));
        g_delta[((size_t)bk * DI + d) * LL + l0 + l] = sp;
    }
}

// ================= K4: selective scan — smem B/C (LDS.64), f32x2, no D-term =================
__global__ void __launch_bounds__(128) k4_scan(const float* __restrict__ A_logs)
{
    int dg = blockIdx.x & 31;
    int bk = blockIdx.x >> 5;
    int k  = bk & 3;
    int b  = bk >> 2;
    int tid  = threadIdx.x;
    int lane = tid & 31;
    int warp = tid >> 5;
    int half = lane >> 4;
    int n    = lane & 15;
    int d    = dg * 8 + warp * 2 + half;

    float aa = -expf(A_logs[((size_t)(k * DI + d)) * Nn + n]) * 1.44269504088896f;
    u64t aa2 = pk2(aa, aa);

    const float* dp = g_delta + ((size_t)bk * DI + d) * LL;
    const float* up = ((((k & 1) == 0) ? g_xhw : g_xwh)) + ((size_t)(b * DI + d)) * LL;
    const float* Bg = g_Bm + (size_t)bk * Nn * LL;
    const float* Cg = g_Cm + (size_t)bk * Nn * LL;
    const bool rev = (k >= 2);

    int ln4 = lane & 15;
    int vsel = (((ln4 >> 3) & 1) << 2) | (((ln4 >> 2) & 1) << 1) | ((ln4 >> 1) & 1);
    bool wlane = ((lane & 1) == 0);

    __shared__ float sB[Nn][66];
    __shared__ float sC[Nn][66];
    __shared__ float yb[4][2][64];

    int crow = tid >> 3;
    int ccol = (tid & 7) * 8;

    float h = 0.f;

#define LOADDU(T, Dq0,Dq1,Uq0,Uq1)                                             \
    {   int _t = (T);                                                          \
        Dq0 = *(const float4*)(dp + _t); Dq1 = *(const float4*)(dp + _t + 4);  \
        if (!rev) { Uq0 = *(const float4*)(up + _t); Uq1 = *(const float4*)(up + _t + 4); } \
        else {                                                                 \
            float4 p0 = *(const float4*)(up + (LL - 8 - _t));                  \
            float4 p1 = *(const float4*)(up + (LL - 4 - _t));                  \
            Uq0.x = p1.w; Uq0.y = p1.z; Uq0.z = p1.y; Uq0.w = p1.x;            \
            Uq1.x = p0.w; Uq1.y = p0.z; Uq1.z = p0.y; Uq1.w = p0.x; } }

    float4 D0, D1, U0, U1;
    LOADDU(0, D0, D1, U0, U1)

    for (int s0 = 0; s0 < LL; s0 += 64) {
        if (s0) __syncthreads();
        {
            float4 b0 = *(const float4*)(Bg + (size_t)crow * LL + s0 + ccol);
            float4 b1 = *(const float4*)(Bg + (size_t)crow * LL + s0 + ccol + 4);
            float4 c0 = *(const float4*)(Cg + (size_t)crow * LL + s0 + ccol);
            float4 c1 = *(const float4*)(Cg + (size_t)crow * LL + s0 + ccol + 4);
            float2* db = (float2*)&sB[crow][0];
            float2* dc = (float2*)&sC[crow][0];
            int p0 = ccol >> 1;
            db[p0+0] = make_float2(b0.x, b0.y); db[p0+1] = make_float2(b0.z, b0.w);
            db[p0+2] = make_float2(b1.x, b1.y); db[p0+3] = make_float2(b1.z, b1.w);
            dc[p0+0] = make_float2(c0.x, c0.y); dc[p0+1] = make_float2(c0.z, c0.w);
            dc[p0+2] = make_float2(c1.x, c1.y); dc[p0+3] = make_float2(c1.z, c1.w);
        }
        __syncthreads();

        #pragma unroll 2
        for (int c8 = 0; c8 < 64; c8 += 8) {
            int t0 = s0 + c8;
            float4 nD0 = D0, nD1 = D1, nU0 = U0, nU1 = U1;
            if (t0 + 8 < LL) LOADDU(t0 + 8, nD0, nD1, nU0, nU1)

            F2U dl2[4], uu2[4];
            dl2[0].f = make_float2(D0.x, D0.y); dl2[1].f = make_float2(D0.z, D0.w);
            dl2[2].f = make_float2(D1.x, D1.y); dl2[3].f = make_float2(D1.z, D1.w);
            uu2[0].f = make_float2(U0.x, U0.y); uu2[1].f = make_float2(U0.z, U0.w);
            uu2[2].f = make_float2(U1.x, U1.y); uu2[3].f = make_float2(U1.z, U1.w);

            const u64t* b64 = (const u64t*)&sB[n][0];
            const u64t* c64 = (const u64t*)&sC[n][0];
            int pb = c8 >> 1;

            F2U ee[4], gg[4], cc[4];
            #pragma unroll
            for (int j = 0; j < 4; j++) {
                ee[j].v = mul2(dl2[j].v, aa2);
                gg[j].v = mul2(mul2(dl2[j].v, uu2[j].v), b64[pb + j]);
                cc[j].v = c64[pb + j];
            }
            float p[8];
            #pragma unroll
            for (int j = 0; j < 4; j++) {
                float e0 = ex2f(ee[j].s[0]);
                float e1 = ex2f(ee[j].s[1]);
                h = fmaf(h, e0, gg[j].s[0]);
                p[2*j]   = h * cc[j].s[0];
                h = fmaf(h, e1, gg[j].s[1]);
                p[2*j+1] = h * cc[j].s[1];
            }
            #pragma unroll
            for (int i = 0; i < 8; i++) p[i] += __shfl_xor_sync(0xffffffffu, p[i], 8);
            float q0 = (lane & 8) ? p[4] : p[0];
            float q1 = (lane & 8) ? p[5] : p[1];
            float q2 = (lane & 8) ? p[6] : p[2];
            float q3 = (lane & 8) ? p[7] : p[3];
            q0 += __shfl_xor_sync(0xffffffffu, q0, 4);
            q1 += __shfl_xor_sync(0xffffffffu, q1, 4);
            q2 += __shfl_xor_sync(0xffffffffu, q2, 4);
            q3 += __shfl_xor_sync(0xffffffffu, q3, 4);
            float r0 = (lane & 4) ? q2 : q0;
            float r1 = (lane & 4) ? q3 : q1;
            r0 += __shfl_xor_sync(0xffffffffu, r0, 2);
            r1 += __shfl_xor_sync(0xffffffffu, r1, 2);
            float s = (lane & 2) ? r1 : r0;
            s += __shfl_xor_sync(0xffffffffu, s, 1);
            if (wlane) yb[warp][half][c8 + vsel] = s;

            D0 = nD0; D1 = nD1; U0 = nU0; U1 = nU1;
        }
        __syncwarp();
        {
            int idx = lane * 4, hs = idx >> 6, off = idx & 63;
            float4 v = *(float4*)&yb[warp][hs][off];
            *(float4*)(g_ys + ((size_t)bk * DI + dg * 8 + warp * 2 + hs) * LL + s0 + off) = v;
        }
        __syncwarp();
    }
#undef LOADDU
}

// ================= K5: combine 4 directions + D*u terms =================
__global__ void k5_combine(const float* __restrict__ Ds)
{
    int hc = blockIdx.x % 6;
    int dc = (blockIdx.x / 6) & 15;
    int b  = blockIdx.x / 96;
    int d0 = dc * 16, h0 = hc * 8;
    __shared__ float s[16][392];
    __shared__ float sD02[16], sD13[16];
    int tid = threadIdx.x;
    const float* y0 = g_ys + ((size_t)(b * 4 + 0) * DI + d0) * LL;
    const float* y1 = g_ys + ((size_t)(b * 4 + 1) * DI + d0) * LL;
    const float* y2 = g_ys + ((size_t)(b * 4 + 2) * DI + d0) * LL;
    const float* y3 = g_ys + ((size_t)(b * 4 + 3) * DI + d0) * LL;
    const float* xh = g_xhw + ((size_t)(b * DI + d0)) * LL;
    const float* xw = g_xwh + ((size_t)(b * DI + d0)) * LL;
    int base = h0 * Ww;

    if (tid < 16) {
        sD02[tid] = Ds[0 * DI + d0 + tid] + Ds[2 * DI + d0 + tid];
        sD13[tid] = Ds[1 * DI + d0 + tid] + Ds[3 * DI + d0 + tid];
    }
    __syncthreads();

    for (int idx = tid; idx < 16 * 384; idx += 256) {
        int d = idx / 384, p = idx % 384;
        int l = base + p;
        s[d][p] = y0[(size_t)d * LL + l] + y2[(size_t)d * LL + (LL - 1 - l)]
                + sD02[d] * xh[(size_t)d * LL + l];
    }
    __syncthreads();
    for (int idx = tid; idx < 16 * 384; idx += 256) {
        int d = idx / 384, p = idx % 384;
        int w = p >> 3, hh = p & 7;
        int t1 = w * Hh + h0 + hh;
        float v = y1[(size_t)d * LL + t1] + y3[(size_t)d * LL + (LL - 1 - t1)]
                + sD13[d] * xw[(size_t)d * LL + t1];
        s[d][hh * Ww + w] += v;
    }
    __syncthreads();
    for (int idx = tid; idx < 384 * 16; idx += 256) {
        int p = idx >> 4, d = idx & 15;
        g_ycomb[((size_t)(b * LL + base + p)) * DI + d0 + d] = s[d][p];
    }
}

// ================= K6: LayerNorm(DI) + SiLU(z) gate =================
__global__ void k6_lngate(const float* __restrict__ og, const float* __restrict__ ob)
{
    int m = blockIdx.x;
    int tid = threadIdx.x;
    float v = g_ycomb[(size_t)m * DI + tid];
    float sm = v, sq = v * v;
    #pragma unroll
    for (int o = 16; o; o >>= 1) {
        sm += __shfl_xor_sync(0xffffffffu, sm, o);
        sq += __shfl_xor_sync(0xffffffffu, sq, o);
    }
    __shared__ float rs1[8], rs2[8];
    int w = tid >> 5, ln = tid & 31;
    if (ln == 0) { rs1[w] = sm; rs2[w] = sq; }
    __syncthreads();
    float ts = 0.f, tq = 0.f;
    #pragma unroll
    for (int i = 0; i < 8; i++) { ts += rs1[i]; tq += rs2[i]; }
    float mean = ts * (1.f / DI);
    float var  = tq * (1.f / DI) - mean * mean;
    float rstd = rsqrtf(var + 1e-5f);
    float zv = g_xz[(size_t)m * 512 + DI + tid];
    float gate = zv * sigmf(zv);
    g_yact[(size_t)m * DI + tid] = ((v - mean) * rstd * og[tid] + ob[tid]) * gate;
}

// ================= K7: out = x + (yact @ out_proj_w^T) (f32x2) =================
__global__ void __launch_bounds__(256) k7_out(const float* __restrict__ Wout,
                                              const float* __restrict__ x,
                                              float* __restrict__ out)
{
    int b  = blockIdx.z;
    int c0 = blockIdx.x * 64;
    int l0 = blockIdx.y * 128;
    __shared__ float As[16][64];
    __shared__ float Bs[16][128];
    int tid = threadIdx.x;
    int tm = tid & 15, tn = tid >> 4;
    int arow = tid >> 2, akq = (tid & 3) * 4;
    int brow = tid >> 1, bkq = (tid & 1) * 8;
    u64t acc2[4][4];
    #pragma unroll
    for (int i = 0; i < 4; i++)
        #pragma unroll
        for (int j = 0; j < 4; j++) acc2[i][j] = 0ULL;

    const float* Y = g_yact + (size_t)b * LL * DI;
    for (int k0 = 0; k0 < DI; k0 += 16) {
        float4 a0 = *(const float4*)(Wout + (size_t)(c0 + arow) * DI + k0 + akq);
        float4 b0 = *(const float4*)(Y + (size_t)(l0 + brow) * DI + k0 + bkq);
        float4 b1 = *(const float4*)(Y + (size_t)(l0 + brow) * DI + k0 + bkq + 4);
        __syncthreads();
        As[akq+0][arow]=a0.x; As[akq+1][arow]=a0.y; As[akq+2][arow]=a0.z; As[akq+3][arow]=a0.w;
        Bs[bkq+0][brow]=b0.x; Bs[bkq+1][brow]=b0.y; Bs[bkq+2][brow]=b0.z; Bs[bkq+3][brow]=b0.w;
        Bs[bkq+4][brow]=b1.x; Bs[bkq+5][brow]=b1.y; Bs[bkq+6][brow]=b1.z; Bs[bkq+7][brow]=b1.w;
        __syncthreads();
        #pragma unroll
        for (int kk = 0; kk < 16; kk++) {
            float4 av  = *(const float4*)&As[kk][tm << 2];
            ulonglong2 bq0 = *(const ulonglong2*)&Bs[kk][tn << 3];
            ulonglong2 bq1 = *(const ulonglong2*)&Bs[kk][(tn << 3) + 4];
            u64t b2[4] = {bq0.x, bq0.y, bq1.x, bq1.y};
            float am[4] = {av.x, av.y, av.z, av.w};
            #pragma unroll
            for (int i = 0; i < 4; i++) {
                u64t a2 = pk2(am[i], am[i]);
                #pragma unroll
                for (int j = 0; j < 4; j++)
                    acc2[i][j] = fma2(a2, b2[j], acc2[i][j]);
            }
        }
    }
    #pragma unroll
    for (int i = 0; i < 4; i++) {
        int c = c0 + (tm << 2) + i;
        size_t off = ((size_t)b * Cc + c) * LL + l0 + (tn << 3);
        ulonglong2 x0 = *(const ulonglong2*)(x + off);
        ulonglong2 x1 = *(const ulonglong2*)(x + off + 4);
        ulonglong2 s0 = make_ulonglong2(add2(acc2[i][0], x0.x), add2(acc2[i][1], x0.y));
        ulonglong2 s1 = make_ulonglong2(add2(acc2[i][2], x1.x), add2(acc2[i][3], x1.y));
        *(ulonglong2*)(out + off)     = s0;
        *(ulonglong2*)(out + off + 4) = s1;
    }
}

extern "C" void kernel_launch(void* const* d_in, const int* in_sizes, int n_in,
                              void* d_out, int out_size)
{
    const float* x          = (const float*)d_in[0];
    const float* ln1_g      = (const float*)d_in[1];
    const float* ln1_b      = (const float*)d_in[2];
    const float* in_proj_w  = (const float*)d_in[3];
    const float* conv_w     = (const float*)d_in[4];
    const float* conv_b     = (const float*)d_in[5];
    const float* x_proj_w   = (const float*)d_in[6];
    const float* dt_w       = (const float*)d_in[7];
    const float* dt_b       = (const float*)d_in[8];
    const float* A_logs     = (const float*)d_in[9];
    const float* Ds         = (const float*)d_in[10];
    const float* outn_g     = (const float*)d_in[11];
    const float* outn_b     = (const float*)d_in[12];
    const float* out_proj_w = (const float*)d_in[13];
    float* out = (float*)d_out;

    k0_ln<<<Bb * Hh, 256>>>(x, ln1_g, ln1_b);
    { dim3 g(BL / 128, 512 / 128); k1_gemm<<<g, 256>>>(in_proj_w); }
    k2_conv<<<Bb * 6 * 16, 256>>>(conv_w, conv_b);
    k3_xproj<<<Bb * Kk * 18, 256>>>(x_proj_w, dt_w, dt_b);
    k4_scan<<<32 * 16, 128>>>(A_logs);
    k5_combine<<<Bb * 16 * 6, 256>>>(Ds);
    k6_lngate<<<BL, 256>>>(outn_g, outn_b);
    { dim3 g(2, 18, Bb); k7_out<<<g, 256>>>(out_proj_w, x, out); }
}

// round 10
// speedup vs baseline: 1.9976x; 1.0180x over previous
#include <cuda_runtime.h>
#include <cuda_bf16.h>
#include <math.h>

#define Bb   4
#define Cc   128
#define DI   256
#define Nn   16
#define Rr   8
#define Kk   4
#define Hh   48
#define Ww   48
#define LL   2304
#define BL   9216

typedef unsigned long long u64t;
union F2U { u64t v; float s[2]; float2 f; };

__device__ __forceinline__ u64t pk2(float lo, float hi){
    u64t r; asm("mov.b64 %0, {%1, %2};" : "=l"(r) : "f"(lo), "f"(hi)); return r;
}
__device__ __forceinline__ u64t fma2(u64t a, u64t b, u64t c){
    u64t r; asm("fma.rn.f32x2 %0, %1, %2, %3;" : "=l"(r) : "l"(a), "l"(b), "l"(c)); return r;
}
__device__ __forceinline__ u64t mul2(u64t a, u64t b){
    u64t r; asm("mul.rn.f32x2 %0, %1, %2;" : "=l"(r) : "l"(a), "l"(b)); return r;
}
__device__ __forceinline__ u64t add2(u64t a, u64t b){
    u64t r; asm("add.rn.f32x2 %0, %1, %2;" : "=l"(r) : "l"(a), "l"(b)); return r;
}
__device__ __forceinline__ float ex2f(float x){
    float r; asm("ex2.approx.f32 %0, %1;" : "=f"(r) : "f"(x)); return r;
}
__device__ __forceinline__ float sigmf(float x){
    return 1.f / (1.f + __expf(-x));
}

// ---------------- scratch ----------------
__device__ float g_xn   [(size_t)BL * Cc];
__device__ float g_xz   [(size_t)BL * 2 * DI];
__device__ float g_xhw  [(size_t)Bb * DI * LL];
__device__ float g_xwh  [(size_t)Bb * DI * LL];
__device__ float g_delta[(size_t)Bb * Kk * DI * LL];
__device__ float g_Bm   [(size_t)Bb * Kk * Nn * LL];
__device__ float g_Cm   [(size_t)Bb * Kk * Nn * LL];
__device__ float g_ys   [(size_t)Bb * Kk * DI * LL];
__device__ float g_ycomb[(size_t)BL * DI];
__device__ float g_yact [(size_t)BL * DI];

// ================= K0: channel LayerNorm -> xn (B*L, C) =================
__global__ void k0_ln(const float* __restrict__ x,
                      const float* __restrict__ lg, const float* __restrict__ lb)
{
    int b = blockIdx.x / Hh;
    int h = blockIdx.x % Hh;
    __shared__ float s[Cc][Ww + 1];
    __shared__ float mu[Ww], rs[Ww];

    const float* xb = x + (size_t)b * Cc * LL + (size_t)h * Ww;
    for (int idx = threadIdx.x; idx < Cc * Ww; idx += 256) {
        int c = idx / Ww, w = idx % Ww;
        s[c][w] = xb[(size_t)c * LL + w];
    }
    __syncthreads();
    if (threadIdx.x < Ww) {
        int w = threadIdx.x;
        float sm = 0.f, sq = 0.f;
        #pragma unroll 8
        for (int c = 0; c < Cc; c++) { float v = s[c][w]; sm += v; sq += v * v; }
        float m = sm * (1.f / Cc);
        float var = sq * (1.f / Cc) - m * m;
        mu[w] = m; rs[w] = rsqrtf(var + 1e-5f);
    }
    __syncthreads();
    float* out = g_xn + ((size_t)(b * LL + h * Ww)) * Cc;
    for (int idx = threadIdx.x; idx < Ww * Cc; idx += 256) {
        int w = idx >> 7, c = idx & 127;
        out[idx] = (s[c][w] - mu[w]) * rs[w] * lg[c] + lb[c];
    }
}

// ================= K1: xz = xn @ in_proj_w^T (f32x2 micro) =================
__global__ void __launch_bounds__(256) k1_gemm(const float* __restrict__ Wp)
{
    __shared__ float As[16][128];
    __shared__ float Bs[16][128];
    int m0 = blockIdx.x * 128, n0 = blockIdx.y * 128;
    int tid = threadIdx.x;
    int tm = tid & 15, tn = tid >> 4;
    int row = tid >> 1, kq = (tid & 1) * 8;
    u64t acc2[8][4];
    #pragma unroll
    for (int i = 0; i < 8; i++)
        #pragma unroll
        for (int j = 0; j < 4; j++) acc2[i][j] = 0ULL;

    for (int k0 = 0; k0 < Cc; k0 += 16) {
        float4 a0 = *(const float4*)(g_xn + (size_t)(m0 + row) * Cc + k0 + kq);
        float4 a1 = *(const float4*)(g_xn + (size_t)(m0 + row) * Cc + k0 + kq + 4);
        float4 b0 = *(const float4*)(Wp   + (size_t)(n0 + row) * Cc + k0 + kq);
        float4 b1 = *(const float4*)(Wp   + (size_t)(n0 + row) * Cc + k0 + kq + 4);
        __syncthreads();
        As[kq+0][row]=a0.x; As[kq+1][row]=a0.y; As[kq+2][row]=a0.z; As[kq+3][row]=a0.w;
        As[kq+4][row]=a1.x; As[kq+5][row]=a1.y; As[kq+6][row]=a1.z; As[kq+7][row]=a1.w;
        Bs[kq+0][row]=b0.x; Bs[kq+1][row]=b0.y; Bs[kq+2][row]=b0.z; Bs[kq+3][row]=b0.w;
        Bs[kq+4][row]=b1.x; Bs[kq+5][row]=b1.y; Bs[kq+6][row]=b1.z; Bs[kq+7][row]=b1.w;
        __syncthreads();
        #pragma unroll
        for (int kk = 0; kk < 16; kk++) {
            float4 av0 = *(const float4*)&As[kk][tm << 3];
            float4 av1 = *(const float4*)&As[kk][(tm << 3) + 4];
            ulonglong2 bq0 = *(const ulonglong2*)&Bs[kk][tn << 3];
            ulonglong2 bq1 = *(const ulonglong2*)&Bs[kk][(tn << 3) + 4];
            u64t b2[4] = {bq0.x, bq0.y, bq1.x, bq1.y};
            float am[8] = {av0.x,av0.y,av0.z,av0.w,av1.x,av1.y,av1.z,av1.w};
            #pragma unroll
            for (int i = 0; i < 8; i++) {
                u64t a2 = pk2(am[i], am[i]);
                #pragma unroll
                for (int j = 0; j < 4; j++)
                    acc2[i][j] = fma2(a2, b2[j], acc2[i][j]);
            }
        }
    }
    #pragma unroll
    for (int i = 0; i < 8; i++) {
        float* o = g_xz + (size_t)(m0 + (tm << 3) + i) * 512 + n0 + (tn << 3);
        ulonglong2 s0 = make_ulonglong2(acc2[i][0], acc2[i][1]);
        ulonglong2 s1 = make_ulonglong2(acc2[i][2], acc2[i][3]);
        *(ulonglong2*)o       = s0;
        *(ulonglong2*)(o + 4) = s1;
    }
}

// ================= K2: depthwise conv3x3 + bias + SiLU -> x_hw, x_wh =================
__global__ void k2_conv(const float* __restrict__ cw, const float* __restrict__ cb)
{
    int bi  = blockIdx.x;
    int dci = bi & 15;
    int hci = (bi >> 4) % 6;
    int b   = bi / 96;
    int d0  = dci * 16;
    int hc  = hci * 8;
    int tid = threadIdx.x;

    __shared__ float sbuf[10][Ww][17];
    __shared__ float wgt[16][9];
    __shared__ float bia[16];

    if (tid < 144) wgt[tid / 9][tid % 9] = cw[(size_t)(d0 + tid / 9) * 9 + tid % 9];
    if (tid >= 144 && tid < 160) bia[tid - 144] = cb[d0 + tid - 144];

    for (int idx = tid; idx < 10 * Ww * 16; idx += 256) {
        int d = idx & 15;
        int rest = idx >> 4;
        int w = rest % Ww;
        int hh = rest / Ww;
        int gh = hc - 1 + hh;
        float v = 0.f;
        if (gh >= 0 && gh < Hh)
            v = g_xz[((size_t)(b * LL + gh * Ww + w)) * 512 + d0 + d];
        sbuf[hh][w][d] = v;
    }
    __syncthreads();

    float outv[24];
    #pragma unroll
    for (int it = 0; it < 24; it++) {
        int idx = tid + it * 256;
        int d = idx / 384;
        int r = idx % 384;
        int h = r / Ww;
        int w = r % Ww;
        float sum = bia[d];
        #pragma unroll
        for (int i = 0; i < 3; i++) {
            #pragma unroll
            for (int j = 0; j < 3; j++) {
                int ww = w + j - 1;
                float xv = (ww >= 0 && ww < Ww) ? sbuf[h + i][ww][d] : 0.f;
                sum = fmaf(wgt[d][i * 3 + j], xv, sum);
            }
        }
        outv[it] = sum * sigmf(sum);
    }
    __syncthreads();
    #pragma unroll
    for (int it = 0; it < 24; it++) {
        int idx = tid + it * 256;
        int d = idx / 384; int r = idx % 384; int h = r / Ww; int w = r % Ww;
        g_xhw[((size_t)(b * DI + d0 + d)) * LL + (hc + h) * Ww + w] = outv[it];
        sbuf[h][w][d] = outv[it];
    }
    __syncthreads();
    for (int it = 0; it < 24; it++) {
        int idx = tid + it * 256;
        int d = idx / 384; int r = idx % 384; int w = r >> 3; int h = r & 7;
        g_xwh[((size_t)(b * DI + d0 + d)) * LL + w * Hh + hc + h] = sbuf[h][w][d];
    }
}

// ================= K3: x_proj + dt + softplus — 64-l tiles, dd-split halves =================
// strides are multiples of 4 so float4 staging stays 16B-aligned.
// smem floats: xu[2720] (uT 32x68 / xd 40x68 overlay), wp[1536], dtw[2048]
__global__ void __launch_bounds__(256) k3_xproj(const float* __restrict__ xpw,
                         const float* __restrict__ dtwg,
                         const float* __restrict__ dtbg)
{
    __shared__ float sm[2720 + 1536 + 2048];
    float* uT  = sm;            // [32][68]
    float* xd  = sm;            // [40][68] overlay (after GEMM)
    float* wp  = sm + 2720;     // [32][4][12]
    float* dtw = sm + 2720 + 1536;

    int lt = blockIdx.x % 36;
    int bk = blockIdx.x / 36;
    int k  = bk & 3;
    int b  = bk >> 2;
    int l0 = lt * 64;
    int tid = threadIdx.x;

    const float* usrc = (((k & 1) == 0) ? g_xhw : g_xwh) + (size_t)b * DI * LL;
    const bool rev = (k >= 2);

    for (int idx = tid; idx < DI * Rr; idx += 256)
        dtw[idx] = dtwg[(size_t)k * DI * Rr + idx];

    int lg    = tid & 31;          // l = 2lg, 2lg+1
    int cg    = (tid >> 5) & 3;    // c group
    int dhalf = tid >> 7;          // 0 or 1: dd sub-range within each 32-chunk

    u64t acc2[2][5];
    #pragma unroll
    for (int li = 0; li < 2; li++)
        #pragma unroll
        for (int jp = 0; jp < 5; jp++) acc2[li][jp] = 0ULL;

    int srow = tid >> 3;          // 0..31
    int scol = (tid & 7) * 8;     // 8 floats each

    for (int dc = 0; dc < DI; dc += 32) {
        __syncthreads();
        for (int idx = tid; idx < 1280; idx += 256) {
            int c = idx >> 5, dd = idx & 31;
            wp[dd * 48 + (c & 3) * 12 + (c >> 2)] = xpw[(size_t)(k * 40 + c) * DI + dc + dd];
        }
        {
            const float* urow = usrc + (size_t)(dc + srow) * LL;
            float* ud = uT + srow * 68;
            if (!rev) {
                float4 v0 = *(const float4*)(urow + l0 + scol);
                float4 v1 = *(const float4*)(urow + l0 + scol + 4);
                *(float4*)(ud + scol)     = v0;
                *(float4*)(ud + scol + 4) = v1;
            } else {
                float4 v0 = *(const float4*)(urow + (LL - 4 - l0 - scol));
                float4 v1 = *(const float4*)(urow + (LL - 8 - l0 - scol));
                *(float4*)(ud + scol)     = make_float4(v0.w, v0.z, v0.y, v0.x);
                *(float4*)(ud + scol + 4) = make_float4(v1.w, v1.z, v1.y, v1.x);
            }
        }
        __syncthreads();
        int db = dhalf * 16;
        #pragma unroll 4
        for (int dd = 0; dd < 16; dd++) {
            int dr = db + dd;
            F2U u2; u2.v = *(const u64t*)(uT + dr * 68 + lg * 2);
            u64t ua = pk2(u2.s[0], u2.s[0]);
            u64t ub = pk2(u2.s[1], u2.s[1]);
            const u64t* w64 = (const u64t*)(wp + dr * 48 + cg * 12);
            #pragma unroll
            for (int jp = 0; jp < 5; jp++) {
                u64t w2 = w64[jp];
                acc2[0][jp] = fma2(ua, w2, acc2[0][jp]);
                acc2[1][jp] = fma2(ub, w2, acc2[1][jp]);
            }
        }
    }
    __syncthreads();
    if (dhalf == 0) {
        #pragma unroll
        for (int jp = 0; jp < 5; jp++)
            #pragma unroll
            for (int li = 0; li < 2; li++) {
                F2U t; t.v = acc2[li][jp];
                xd[(cg + 8 * jp) * 68 + lg * 2 + li]     = t.s[0];
                xd[(cg + 8 * jp + 4) * 68 + lg * 2 + li] = t.s[1];
            }
    }
    __syncthreads();
    if (dhalf == 1) {
        #pragma unroll
        for (int jp = 0; jp < 5; jp++)
            #pragma unroll
            for (int li = 0; li < 2; li++) {
                F2U t; t.v = acc2[li][jp];
                xd[(cg + 8 * jp) * 68 + lg * 2 + li]     += t.s[0];
                xd[(cg + 8 * jp + 4) * 68 + lg * 2 + li] += t.s[1];
            }
    }
    __syncthreads();

    for (int idx = tid; idx < Nn * 64; idx += 256) {
        int nn = idx >> 6, li = idx & 63;
        g_Bm[((size_t)bk * Nn + nn) * LL + l0 + li] = xd[(Rr + nn) * 68 + li];
        g_Cm[((size_t)bk * Nn + nn) * LL + l0 + li] = xd[(Rr + Nn + nn) * 68 + li];
    }

    int l = tid & 63, q = tid >> 6;    // q in 0..3, each covers 64 d
    u64t dtr2[4];
    #pragma unroll
    for (int r = 0; r < 4; r++)
        dtr2[r] = pk2(xd[(2 * r) * 68 + l], xd[(2 * r + 1) * 68 + l]);

    const float* dtb = dtbg + k * DI;
    #pragma unroll 2
    for (int dd = 0; dd < 64; dd++) {
        int d = (q << 6) + dd;
        ulonglong2 wq0 = *(const ulonglong2*)(dtw + d * 8);
        ulonglong2 wq1 = *(const ulonglong2*)(dtw + d * 8 + 4);
        u64t m = fma2(wq0.x, dtr2[0],
                  fma2(wq0.y, dtr2[1],
                   fma2(wq1.x, dtr2[2],
                    mul2(wq1.y, dtr2[3]))));
        F2U t; t.v = m;
        float a = dtb[d] + t.s[0] + t.s[1];
        float sp = fmaxf(a, 0.f) + __logf(1.f + __expf(-fabsf(a)));
        g_delta[((size_t)bk * DI + d) * LL + l0 + l] = sp;
    }
}

// ================= K4: selective scan — smem B/C, clamped prefetch =================
__global__ void __launch_bounds__(128) k4_scan(const float* __restrict__ A_logs)
{
    int dg = blockIdx.x & 31;
    int bk = blockIdx.x >> 5;
    int k  = bk & 3;
    int b  = bk >> 2;
    int tid  = threadIdx.x;
    int lane = tid & 31;
    int warp = tid >> 5;
    int half = lane >> 4;
    int n    = lane & 15;
    int d    = dg * 8 + warp * 2 + half;

    float aa = -expf(A_logs[((size_t)(k * DI + d)) * Nn + n]) * 1.44269504088896f;
    u64t aa2 = pk2(aa, aa);

    const float* dp = g_delta + ((size_t)bk * DI + d) * LL;
    const float* up = ((((k & 1) == 0) ? g_xhw : g_xwh)) + ((size_t)(b * DI + d)) * LL;
    const float* Bg = g_Bm + (size_t)bk * Nn * LL;
    const float* Cg = g_Cm + (size_t)bk * Nn * LL;
    const bool rev = (k >= 2);

    int ln4 = lane & 15;
    int vsel = (((ln4 >> 3) & 1) << 2) | (((ln4 >> 2) & 1) << 1) | ((ln4 >> 1) & 1);
    bool wlane = ((lane & 1) == 0);

    __shared__ float sB[Nn][66];
    __shared__ float sC[Nn][66];
    __shared__ float yb[4][2][64];

    int crow = tid >> 3;
    int ccol = (tid & 7) * 8;

    float h = 0.f;

#define LOADDU(T, Dq0,Dq1,Uq0,Uq1)                                             \
    {   int _t = (T);                                                          \
        Dq0 = *(const float4*)(dp + _t); Dq1 = *(const float4*)(dp + _t + 4);  \
        if (!rev) { Uq0 = *(const float4*)(up + _t); Uq1 = *(const float4*)(up + _t + 4); } \
        else {                                                                 \
            float4 p0 = *(const float4*)(up + (LL - 8 - _t));                  \
            float4 p1 = *(const float4*)(up + (LL - 4 - _t));                  \
            Uq0.x = p1.w; Uq0.y = p1.z; Uq0.z = p1.y; Uq0.w = p1.x;            \
            Uq1.x = p0.w; Uq1.y = p0.z; Uq1.z = p0.y; Uq1.w = p0.x; } }

    float4 D0, D1, U0, U1;
    LOADDU(0, D0, D1, U0, U1)

    for (int s0 = 0; s0 < LL; s0 += 64) {
        if (s0) __syncthreads();
        {
            float4 b0 = *(const float4*)(Bg + (size_t)crow * LL + s0 + ccol);
            float4 b1 = *(const float4*)(Bg + (size_t)crow * LL + s0 + ccol + 4);
            float4 c0 = *(const float4*)(Cg + (size_t)crow * LL + s0 + ccol);
            float4 c1 = *(const float4*)(Cg + (size_t)crow * LL + s0 + ccol + 4);
            float2* db = (float2*)&sB[crow][0];
            float2* dc = (float2*)&sC[crow][0];
            int p0 = ccol >> 1;
            db[p0+0] = make_float2(b0.x, b0.y); db[p0+1] = make_float2(b0.z, b0.w);
            db[p0+2] = make_float2(b1.x, b1.y); db[p0+3] = make_float2(b1.z, b1.w);
            dc[p0+0] = make_float2(c0.x, c0.y); dc[p0+1] = make_float2(c0.z, c0.w);
            dc[p0+2] = make_float2(c1.x, c1.y); dc[p0+3] = make_float2(c1.z, c1.w);
        }
        __syncthreads();

        #pragma unroll 2
        for (int c8 = 0; c8 < 64; c8 += 8) {
            int t0 = s0 + c8;
            int tn = t0 + 8;
            if (tn >= LL) tn = 0;              // clamped (discarded) prefetch
            float4 nD0, nD1, nU0, nU1;
            LOADDU(tn, nD0, nD1, nU0, nU1)

            F2U dl2[4], uu2[4];
            dl2[0].f = make_float2(D0.x, D0.y); dl2[1].f = make_float2(D0.z, D0.w);
            dl2[2].f = make_float2(D1.x, D1.y); dl2[3].f = make_float2(D1.z, D1.w);
            uu2[0].f = make_float2(U0.x, U0.y); uu2[1].f = make_float2(U0.z, U0.w);
            uu2[2].f = make_float2(U1.x, U1.y); uu2[3].f = make_float2(U1.z, U1.w);

            const u64t* b64 = (const u64t*)&sB[n][0];
            const u64t* c64 = (const u64t*)&sC[n][0];
            int pb = c8 >> 1;

            F2U ee[4], gg[4], cc[4];
            #pragma unroll
            for (int j = 0; j < 4; j++) {
                ee[j].v = mul2(dl2[j].v, aa2);
                gg[j].v = mul2(mul2(dl2[j].v, uu2[j].v), b64[pb + j]);
                cc[j].v = c64[pb + j];
            }
            float p[8];
            #pragma unroll
            for (int j = 0; j < 4; j++) {
                float e0 = ex2f(ee[j].s[0]);
                float e1 = ex2f(ee[j].s[1]);
                h = fmaf(h, e0, gg[j].s[0]);
                p[2*j]   = h * cc[j].s[0];
                h = fmaf(h, e1, gg[j].s[1]);
                p[2*j+1] = h * cc[j].s[1];
            }
            #pragma unroll
            for (int i = 0; i < 8; i++) p[i] += __shfl_xor_sync(0xffffffffu, p[i], 8);
            float q0 = (lane & 8) ? p[4] : p[0];
            float q1 = (lane & 8) ? p[5] : p[1];
            float q2 = (lane & 8) ? p[6] : p[2];
            float q3 = (lane & 8) ? p[7] : p[3];
            q0 += __shfl_xor_sync(0xffffffffu, q0, 4);
            q1 += __shfl_xor_sync(0xffffffffu, q1, 4);
            q2 += __shfl_xor_sync(0xffffffffu, q2, 4);
            q3 += __shfl_xor_sync(0xffffffffu, q3, 4);
            float r0 = (lane & 4) ? q2 : q0;
            float r1 = (lane & 4) ? q3 : q1;
            r0 += __shfl_xor_sync(0xffffffffu, r0, 2);
            r1 += __shfl_xor_sync(0xffffffffu, r1, 2);
            float s = (lane & 2) ? r1 : r0;
            s += __shfl_xor_sync(0xffffffffu, s, 1);
            if (wlane) yb[warp][half][c8 + vsel] = s;

            D0 = nD0; D1 = nD1; U0 = nU0; U1 = nU1;
        }
        __syncwarp();
        {
            int idx = lane * 4, hs = idx >> 6, off = idx & 63;
            float4 v = *(float4*)&yb[warp][hs][off];
            *(float4*)(g_ys + ((size_t)bk * DI + dg * 8 + warp * 2 + hs) * LL + s0 + off) = v;
        }
        __syncwarp();
    }
#undef LOADDU
}

// ================= K5: combine 4 directions + D*u terms =================
__global__ void k5_combine(const float* __restrict__ Ds)
{
    int hc = blockIdx.x % 6;
    int dc = (blockIdx.x / 6) & 15;
    int b  = blockIdx.x / 96;
    int d0 = dc * 16, h0 = hc * 8;
    __shared__ float s[16][392];
    __shared__ float sD02[16], sD13[16];
    int tid = threadIdx.x;
    const float* y0 = g_ys + ((size_t)(b * 4 + 0) * DI + d0) * LL;
    const float* y1 = g_ys + ((size_t)(b * 4 + 1) * DI + d0) * LL;
    const float* y2 = g_ys + ((size_t)(b * 4 + 2) * DI + d0) * LL;
    const float* y3 = g_ys + ((size_t)(b * 4 + 3) * DI + d0) * LL;
    const float* xh = g_xhw + ((size_t)(b * DI + d0)) * LL;
    const float* xw = g_xwh + ((size_t)(b * DI + d0)) * LL;
    int base = h0 * Ww;

    if (tid < 16) {
        sD02[tid] = Ds[0 * DI + d0 + tid] + Ds[2 * DI + d0 + tid];
        sD13[tid] = Ds[1 * DI + d0 + tid] + Ds[3 * DI + d0 + tid];
    }
    __syncthreads();

    for (int idx = tid; idx < 16 * 384; idx += 256) {
        int d = idx / 384, p = idx % 384;
        int l = base + p;
        s[d][p] = y0[(size_t)d * LL + l] + y2[(size_t)d * LL + (LL - 1 - l)]
                + sD02[d] * xh[(size_t)d * LL + l];
    }
    __syncthreads();
    for (int idx = tid; idx < 16 * 384; idx += 256) {
        int d = idx / 384, p = idx % 384;
        int w = p >> 3, hh = p & 7;
        int t1 = w * Hh + h0 + hh;
        float v = y1[(size_t)d * LL + t1] + y3[(size_t)d * LL + (LL - 1 - t1)]
                + sD13[d] * xw[(size_t)d * LL + t1];
        s[d][hh * Ww + w] += v;
    }
    __syncthreads();
    for (int idx = tid; idx < 384 * 16; idx += 256) {
        int p = idx >> 4, d = idx & 15;
        g_ycomb[((size_t)(b * LL + base + p)) * DI + d0 + d] = s[d][p];
    }
}

// ================= K6: LayerNorm(DI) + SiLU(z) gate =================
__global__ void k6_lngate(const float* __restrict__ og, const float* __restrict__ ob)
{
    int m = blockIdx.x;
    int tid = threadIdx.x;
    float v = g_ycomb[(size_t)m * DI + tid];
    float sm = v, sq = v * v;
    #pragma unroll
    for (int o = 16; o; o >>= 1) {
        sm += __shfl_xor_sync(0xffffffffu, sm, o);
        sq += __shfl_xor_sync(0xffffffffu, sq, o);
    }
    __shared__ float rs1[8], rs2[8];
    int w = tid >> 5, ln = tid & 31;
    if (ln == 0) { rs1[w] = sm; rs2[w] = sq; }
    __syncthreads();
    float ts = 0.f, tq = 0.f;
    #pragma unroll
    for (int i = 0; i < 8; i++) { ts += rs1[i]; tq += rs2[i]; }
    float mean = ts * (1.f / DI);
    float var  = tq * (1.f / DI) - mean * mean;
    float rstd = rsqrtf(var + 1e-5f);
    float zv = g_xz[(size_t)m * 512 + DI + tid];
    float gate = zv * sigmf(zv);
    g_yact[(size_t)m * DI + tid] = ((v - mean) * rstd * og[tid] + ob[tid]) * gate;
}

// ================= K7: out = x + (yact @ out_proj_w^T) (f32x2) =================
__global__ void __launch_bounds__(256) k7_out(const float* __restrict__ Wout,
                                              const float* __restrict__ x,
                                              float* __restrict__ out)
{
    int b  = blockIdx.z;
    int c0 = blockIdx.x * 64;
    int l0 = blockIdx.y * 128;
    __shared__ float As[16][64];
    __shared__ float Bs[16][128];
    int tid = threadIdx.x;
    int tm = tid & 15, tn = tid >> 4;
    int arow = tid >> 2, akq = (tid & 3) * 4;
    int brow = tid >> 1, bkq = (tid & 1) * 8;
    u64t acc2[4][4];
    #pragma unroll
    for (int i = 0; i < 4; i++)
        #pragma unroll
        for (int j = 0; j < 4; j++) acc2[i][j] = 0ULL;

    const float* Y = g_yact + (size_t)b * LL * DI;
    for (int k0 = 0; k0 < DI; k0 += 16) {
        float4 a0 = *(const float4*)(Wout + (size_t)(c0 + arow) * DI + k0 + akq);
        float4 b0 = *(const float4*)(Y + (size_t)(l0 + brow) * DI + k0 + bkq);
        float4 b1 = *(const float4*)(Y + (size_t)(l0 + brow) * DI + k0 + bkq + 4);
        __syncthreads();
        As[akq+0][arow]=a0.x; As[akq+1][arow]=a0.y; As[akq+2][arow]=a0.z; As[akq+3][arow]=a0.w;
        Bs[bkq+0][brow]=b0.x; Bs[bkq+1][brow]=b0.y; Bs[bkq+2][brow]=b0.z; Bs[bkq+3][brow]=b0.w;
        Bs[bkq+4][brow]=b1.x; Bs[bkq+5][brow]=b1.y; Bs[bkq+6][brow]=b1.z; Bs[bkq+7][brow]=b1.w;
        __syncthreads();
        #pragma unroll
        for (int kk = 0; kk < 16; kk++) {
            float4 av  = *(const float4*)&As[kk][tm << 2];
            ulonglong2 bq0 = *(const ulonglong2*)&Bs[kk][tn << 3];
            ulonglong2 bq1 = *(const ulonglong2*)&Bs[kk][(tn << 3) + 4];
            u64t b2[4] = {bq0.x, bq0.y, bq1.x, bq1.y};
            float am[4] = {av.x, av.y, av.z, av.w};
            #pragma unroll
            for (int i = 0; i < 4; i++) {
                u64t a2 = pk2(am[i], am[i]);
                #pragma unroll
                for (int j = 0; j < 4; j++)
                    acc2[i][j] = fma2(a2, b2[j], acc2[i][j]);
            }
        }
    }
    #pragma unroll
    for (int i = 0; i < 4; i++) {
        int c = c0 + (tm << 2) + i;
        size_t off = ((size_t)b * Cc + c) * LL + l0 + (tn << 3);
        ulonglong2 x0 = *(const ulonglong2*)(x + off);
        ulonglong2 x1 = *(const ulonglong2*)(x + off + 4);
        ulonglong2 s0 = make_ulonglong2(add2(acc2[i][0], x0.x), add2(acc2[i][1], x0.y));
        ulonglong2 s1 = make_ulonglong2(add2(acc2[i][2], x1.x), add2(acc2[i][3], x1.y));
        *(ulonglong2*)(out + off)     = s0;
        *(ulonglong2*)(out + off + 4) = s1;
    }
}

extern "C" void kernel_launch(void* const* d_in, const int* in_sizes, int n_in,
                              void* d_out, int out_size)
{
    const float* x          = (const float*)d_in[0];
    const float* ln1_g      = (const float*)d_in[1];
    const float* ln1_b      = (const float*)d_in[2];
    const float* in_proj_w  = (const float*)d_in[3];
    const float* conv_w     = (const float*)d_in[4];
    const float* conv_b     = (const float*)d_in[5];
    const float* x_proj_w   = (const float*)d_in[6];
    const float* dt_w       = (const float*)d_in[7];
    const float* dt_b       = (const float*)d_in[8];
    const float* A_logs     = (const float*)d_in[9];
    const float* Ds         = (const float*)d_in[10];
    const float* outn_g     = (const float*)d_in[11];
    const float* outn_b     = (const float*)d_in[12];
    const float* out_proj_w = (const float*)d_in[13];
    float* out = (float*)d_out;

    k0_ln<<<Bb * Hh, 256>>>(x, ln1_g, ln1_b);
    { dim3 g(BL / 128, 512 / 128); k1_gemm<<<g, 256>>>(in_proj_w); }
    k2_conv<<<Bb * 6 * 16, 256>>>(conv_w, conv_b);
    k3_xproj<<<Bb * Kk * 36, 256>>>(x_proj_w, dt_w, dt_b);
    k4_scan<<<32 * 16, 128>>>(A_logs);
    k5_combine<<<Bb * 16 * 6, 256>>>(Ds);
    k6_lngate<<<BL, 256>>>(outn_g, outn_b);
    { dim3 g(2, 18, Bb); k7_out<<<g, 256>>>(out_proj_w, x, out); }
}